// round 12
// baseline (speedup 1.0000x reference)
#include <cuda_runtime.h>
#include <math.h>
#include <stdint.h>

#define B_   2
#define S_   2048
#define D_   1024
#define H_   16
#define DH_  64
#define DFF_ 4096
#define M_   (B_*S_)    // 4096 tokens
#define QKVD 3072

// ---------------- scratch (static device allocations) ---------------------------
__device__ float g_ln [M_ * D_];
__device__ float g_qkv[(size_t)M_ * QKVD];              // 48 MB
__device__ float g_ctx[M_ * D_];
__device__ float g_h  [M_ * D_];
__device__ float g_ffn[(size_t)M_ * DFF_];              // 64 MB
__device__ float g_pool[4 * 1024 * 1024];               // packed QKV weights

// ---------------- helpers --------------------------------------------------------
__device__ __forceinline__ unsigned f2tf32(float x) {
    unsigned r;
    asm("cvt.rna.tf32.f32 %0, %1;" : "=r"(r) : "f"(x));
    return r;
}
__device__ __forceinline__ float rnd_tf32(float x) {
    return __uint_as_float(f2tf32(x));
}
__device__ __forceinline__ void mma_tf32(float* c, const unsigned* a, const unsigned* b) {
    asm volatile(
        "mma.sync.aligned.m16n8k8.row.col.f32.tf32.tf32.f32 "
        "{%0,%1,%2,%3}, {%4,%5,%6,%7}, {%8,%9}, {%0,%1,%2,%3};"
        : "+f"(c[0]), "+f"(c[1]), "+f"(c[2]), "+f"(c[3])
        : "r"(a[0]), "r"(a[1]), "r"(a[2]), "r"(a[3]), "r"(b[0]), "r"(b[1]));
}
__device__ __forceinline__ void cpasync16(float* smem, const float* gmem) {
    unsigned s = (unsigned)__cvta_generic_to_shared(smem);
    asm volatile("cp.async.cg.shared.global [%0], [%1], 16;" :: "r"(s), "l"(gmem));
}

// ---------------- weight prep: pack QKV into [1024, 3072] (rounded, free) --------
__global__ void pack_round_kernel(const float* __restrict__ in,
                                  float* __restrict__ out, int off4)
{
    int i = blockIdx.x * 256 + threadIdx.x;     // over 1024*256 float4s
    int k = i >> 8, n4 = i & 255;
    float4 a = ((const float4*)in)[i];
    a.x = rnd_tf32(a.x); a.y = rnd_tf32(a.y);
    a.z = rnd_tf32(a.z); a.w = rnd_tf32(a.w);
    ((float4*)(out + (size_t)k * QKVD))[off4 + n4] = a;
}

// ---------------- LayerNorm (output tf32-rounded) --------------------------------
__global__ void ln_kernel(const float* __restrict__ x,
                          const float* __restrict__ sc,
                          const float* __restrict__ sh,
                          float* __restrict__ out)
{
    int row = blockIdx.x;
    const float* xr = x + (size_t)row * D_;
    float* outr = out + (size_t)row * D_;

    float s = 0.f, s2 = 0.f;
    for (int j = threadIdx.x; j < D_; j += blockDim.x) {
        float v = xr[j];
        s += v; s2 += v * v;
    }
    __shared__ float rs[256], rs2[256];
    rs[threadIdx.x] = s; rs2[threadIdx.x] = s2;
    __syncthreads();
    for (int o = 128; o > 0; o >>= 1) {
        if (threadIdx.x < o) {
            rs [threadIdx.x] += rs [threadIdx.x + o];
            rs2[threadIdx.x] += rs2[threadIdx.x + o];
        }
        __syncthreads();
    }
    float mean = rs[0] * (1.0f / D_);
    float var  = rs2[0] * (1.0f / D_) - mean * mean;
    float inv  = rsqrtf(var + 1e-5f);
    for (int j = threadIdx.x; j < D_; j += blockDim.x)
        outr[j] = rnd_tf32((xr[j] - mean) * inv * sc[j] + sh[j]);
}

// ---------------- TF32 mma.sync GEMM: 4 warps @ 64x64, 2-stage-per-sync ring -----
// C(MxN) = A(MxK) @ B(KxN). One wait+__syncthreads per 32 K.
#define AS_STRIDE 20
#define BS_STRIDE 136
#define AS_BUF (128 * AS_STRIDE)
#define BS_BUF (16 * BS_STRIDE)
#define STG_FLOATS (AS_BUF + BS_BUF)
#define GSTAGES 4
#define GEMM_SMEM (GSTAGES * STG_FLOATS * 4)

__global__ __launch_bounds__(128, 2)
void sgemm_tf32_kernel(const float* __restrict__ A,
                       const float* __restrict__ Bm,
                       const float* __restrict__ bias,   // may be null
                       const float* __restrict__ res,    // may be null
                       float* __restrict__ C,
                       int M, int N, int K, int gelu, int roundOut)
{
    extern __shared__ float sm[];

    const int tid  = threadIdx.x;
    const int lane = tid & 31;
    const int warp = tid >> 5;       // 0..3
    const int g    = lane >> 2;
    const int t    = lane & 3;
    const int warpRow = warp >> 1;
    const int warpCol = warp & 1;

    const int rowBase = blockIdx.y * 128;
    const int colBase = blockIdx.x * 128;

    float acc[4][8][4];
    #pragma unroll
    for (int i = 0; i < 4; i++)
        #pragma unroll
        for (int j = 0; j < 8; j++)
            #pragma unroll
            for (int r = 0; r < 4; r++) acc[i][j][r] = 0.f;

    const int nIter2 = K / 32;

    // prologue: fill stages 0,1 (k = 0..31), single commit group
    #pragma unroll
    for (int s2 = 0; s2 < 2; s2++) {
        float* As = sm + s2 * STG_FLOATS;
        float* Bs = As + AS_BUF;
        int k0 = s2 * 16;
        #pragma unroll
        for (int u = 0; u < 4; u++) {
            int idx = u * 128 + tid;
            int ar = idx >> 2, ac = (idx & 3) * 4;
            cpasync16(&As[ar * AS_STRIDE + ac], &A[(size_t)(rowBase + ar) * K + k0 + ac]);
            int br = idx >> 5, bc = (idx & 31) * 4;
            cpasync16(&Bs[br * BS_STRIDE + bc], &Bm[(size_t)(k0 + br) * N + colBase + bc]);
        }
    }
    asm volatile("cp.async.commit_group;");

    for (int it = 0; it < nIter2; ++it) {
        asm volatile("cp.async.wait_group 0;");
        __syncthreads();

        // prefetch next 32-K pair into the other super-stage (overlaps compute)
        if (it + 1 < nIter2) {
            int base = ((it + 1) & 1) * 2;
            #pragma unroll
            for (int s2 = 0; s2 < 2; s2++) {
                float* As = sm + (base + s2) * STG_FLOATS;
                float* Bs = As + AS_BUF;
                int k0 = (it + 1) * 32 + s2 * 16;
                #pragma unroll
                for (int u = 0; u < 4; u++) {
                    int idx = u * 128 + tid;
                    int ar = idx >> 2, ac = (idx & 3) * 4;
                    cpasync16(&As[ar * AS_STRIDE + ac], &A[(size_t)(rowBase + ar) * K + k0 + ac]);
                    int br = idx >> 5, bc = (idx & 31) * 4;
                    cpasync16(&Bs[br * BS_STRIDE + bc], &Bm[(size_t)(k0 + br) * N + colBase + bc]);
                }
            }
            asm volatile("cp.async.commit_group;");
        }

        const int pbase = (it & 1) * 2;
        #pragma unroll
        for (int s2 = 0; s2 < 2; s2++) {
            const float* As_ = sm + (pbase + s2) * STG_FLOATS;
            const float* Bs_ = As_ + AS_BUF;

            #pragma unroll
            for (int ks = 0; ks < 2; ks++) {
                const int k = ks * 8;
                unsigned afr[4][4], bfr[8][2];
                #pragma unroll
                for (int mt = 0; mt < 4; mt++) {
                    int m = warpRow * 64 + mt * 16 + g;
                    afr[mt][0] = __float_as_uint(As_[m * AS_STRIDE + k + t]);
                    afr[mt][1] = __float_as_uint(As_[(m + 8) * AS_STRIDE + k + t]);
                    afr[mt][2] = __float_as_uint(As_[m * AS_STRIDE + k + t + 4]);
                    afr[mt][3] = __float_as_uint(As_[(m + 8) * AS_STRIDE + k + t + 4]);
                }
                #pragma unroll
                for (int nt = 0; nt < 8; nt++) {
                    int n = warpCol * 64 + nt * 8 + g;
                    bfr[nt][0] = __float_as_uint(Bs_[(k + t) * BS_STRIDE + n]);
                    bfr[nt][1] = __float_as_uint(Bs_[(k + t + 4) * BS_STRIDE + n]);
                }
                #pragma unroll
                for (int mt = 0; mt < 4; mt++)
                    #pragma unroll
                    for (int nt = 0; nt < 8; nt++)
                        mma_tf32(acc[mt][nt], afr[mt], bfr[nt]);
            }
        }
    }

    #pragma unroll
    for (int mt = 0; mt < 4; mt++) {
        #pragma unroll
        for (int nt = 0; nt < 8; nt++) {
            int r0 = rowBase + warpRow * 64 + mt * 16 + g;
            int c0 = colBase + warpCol * 64 + nt * 8 + 2 * t;
            #pragma unroll
            for (int half = 0; half < 2; half++) {
                int r = r0 + half * 8;
                float v0 = acc[mt][nt][2*half], v1 = acc[mt][nt][2*half+1];
                if (bias) { v0 += bias[c0]; v1 += bias[c0 + 1]; }
                if (gelu) {
                    float t0 = 1.5957691216057308f * v0 + 0.0713548162726009f * v0 * v0 * v0;
                    v0 = __fdividef(v0, 1.f + __expf(-t0));
                    float t1 = 1.5957691216057308f * v1 + 0.0713548162726009f * v1 * v1 * v1;
                    v1 = __fdividef(v1, 1.f + __expf(-t1));
                }
                if (res) {
                    float2 rr = *(const float2*)&res[(size_t)r * N + c0];
                    v0 += rr.x; v1 += rr.y;
                }
                if (roundOut) { v0 = rnd_tf32(v0); v1 = rnd_tf32(v1); }
                *(float2*)&C[(size_t)r * N + c0] = make_float2(v0, v1);
            }
        }
    }
}

// ---------------- fused flash attention: 4 warps, 32 q-rows/warp (R11 winner) ----
#define SK 68
#define SV 72
#define KVBUF (64*SK + 64*SV)
#define FLASH_SMEM ((128*SK + 2*KVBUF) * 4)

__global__ __launch_bounds__(128)
void flash_attn_kernel(const float* __restrict__ qkv, float* __restrict__ ctx)
{
    extern __shared__ float sm[];
    float* Ps = sm;                       // 128 x SK (Q prologue, then P)
    float* KV0 = sm + 128 * SK;           // double-buffered K/V tiles

    const int qt = (int)(gridDim.x - 1) - (int)blockIdx.x;   // big tiles first
    const int bh = blockIdx.y;
    const int b = bh >> 4, h = bh & 15;
    const float* qb = qkv + (size_t)b * S_ * QKVD + h * DH_;
    const float* kb = qb + D_;
    const float* vb = qb + 2 * D_;
    float* cb = ctx + (size_t)b * S_ * D_ + h * DH_;

    const int tid = threadIdx.x, lane = tid & 31, warp = tid >> 5;   // warp 0..3
    const int g = lane >> 2, t = lane & 3;
    const int rowBase = qt * 128;
    const int wrow = warp * 32;            // 32 q-rows per warp
    const int ktmax = 2 * qt + 2;

    // ---- Q prologue: each warp stages its own 32 rows
    #pragma unroll
    for (int u = 0; u < 16; u++) {
        int idx = u * 32 + lane;
        int r = idx >> 4, c4 = (idx & 15) * 4;
        cpasync16(&Ps[(wrow + r) * SK + c4],
                  &qb[(size_t)(rowBase + wrow + r) * QKVD + c4]);
    }
    asm volatile("cp.async.commit_group;");
    asm volatile("cp.async.wait_group 0;");
    __syncwarp();

    unsigned qa[2][8][4];
    #pragma unroll
    for (int mt = 0; mt < 2; mt++) {
        int wr = wrow + 16 * mt;
        #pragma unroll
        for (int ks = 0; ks < 8; ks++) {
            qa[mt][ks][0] = __float_as_uint(0.125f * Ps[(wr + g)     * SK + 8*ks + t]);
            qa[mt][ks][1] = __float_as_uint(0.125f * Ps[(wr + g + 8) * SK + 8*ks + t]);
            qa[mt][ks][2] = __float_as_uint(0.125f * Ps[(wr + g)     * SK + 8*ks + t + 4]);
            qa[mt][ks][3] = __float_as_uint(0.125f * Ps[(wr + g + 8) * SK + 8*ks + t + 4]);
        }
    }

    // ---- prefetch KV tile 0 into buffer 0
    {
        float* Ks = KV0;
        float* Vs = KV0 + 64 * SK;
        #pragma unroll
        for (int u = 0; u < 8; u++) {
            int idx = u * 128 + tid;
            int r = idx >> 4, c4 = (idx & 15) * 4;
            cpasync16(&Ks[r * SK + c4], &kb[(size_t)r * QKVD + c4]);
            cpasync16(&Vs[r * SV + c4], &vb[(size_t)r * QKVD + c4]);
        }
        asm volatile("cp.async.commit_group;");
    }

    float o[2][8][4];
    #pragma unroll
    for (int mt = 0; mt < 2; mt++)
        #pragma unroll
        for (int nt = 0; nt < 8; nt++)
            #pragma unroll
            for (int e = 0; e < 4; e++) o[mt][nt][e] = 0.f;
    float mrow[2][2] = { {-1e30f, -1e30f}, {-1e30f, -1e30f} };
    float lrow[2][2] = { {0.f, 0.f}, {0.f, 0.f} };
    int rown[2][2];
    #pragma unroll
    for (int mt = 0; mt < 2; mt++) {
        rown[mt][0] = rowBase + wrow + 16 * mt + g;
        rown[mt][1] = rown[mt][0] + 8;
    }

    for (int kt = 0; kt < ktmax; kt++) {
        __syncthreads();                       // prev compute done on buf^1
        if (kt + 1 < ktmax) {                  // prefetch next tile into buf^1
            float* Ks = KV0 + ((kt + 1) & 1) * KVBUF;
            float* Vs = Ks + 64 * SK;
            #pragma unroll
            for (int u = 0; u < 8; u++) {
                int idx = u * 128 + tid;
                int r = idx >> 4, c4 = (idx & 15) * 4;
                cpasync16(&Ks[r * SK + c4], &kb[(size_t)((kt + 1) * 64 + r) * QKVD + c4]);
                cpasync16(&Vs[r * SV + c4], &vb[(size_t)((kt + 1) * 64 + r) * QKVD + c4]);
            }
            asm volatile("cp.async.commit_group;");
            asm volatile("cp.async.wait_group 1;");
        } else {
            asm volatile("cp.async.wait_group 0;");
        }
        __syncthreads();                       // tile kt visible to all

        const float* Ks = KV0 + (kt & 1) * KVBUF;
        const float* Vs = Ks + 64 * SK;

        // ---- S = Q K^T: each K fragment reused across both m-tiles
        float sc[2][8][4];
        #pragma unroll
        for (int mt = 0; mt < 2; mt++)
            #pragma unroll
            for (int nt = 0; nt < 8; nt++)
                sc[mt][nt][0] = sc[mt][nt][1] = sc[mt][nt][2] = sc[mt][nt][3] = 0.f;
        #pragma unroll
        for (int nt = 0; nt < 8; nt++) {
            #pragma unroll
            for (int ks = 0; ks < 8; ks++) {
                unsigned bb[2];
                bb[0] = __float_as_uint(Ks[(8*nt + g) * SK + 8*ks + t]);
                bb[1] = __float_as_uint(Ks[(8*nt + g) * SK + 8*ks + t + 4]);
                mma_tf32(sc[0][nt], qa[0][ks], bb);
                mma_tf32(sc[1][nt], qa[1][ks], bb);
            }
        }

        // ---- mask + online softmax (per m-tile)
        const int colb = kt * 64 + 2 * t;
        #pragma unroll
        for (int mt = 0; mt < 2; mt++) {
            float mx0 = -1e30f, mx1 = -1e30f;
            #pragma unroll
            for (int nt = 0; nt < 8; nt++) {
                int c0 = colb + 8 * nt;
                float v0 = sc[mt][nt][0]; if (c0     > rown[mt][0]) v0 = -1e30f;
                float v1 = sc[mt][nt][1]; if (c0 + 1 > rown[mt][0]) v1 = -1e30f;
                float v2 = sc[mt][nt][2]; if (c0     > rown[mt][1]) v2 = -1e30f;
                float v3 = sc[mt][nt][3]; if (c0 + 1 > rown[mt][1]) v3 = -1e30f;
                sc[mt][nt][0] = v0; sc[mt][nt][1] = v1;
                sc[mt][nt][2] = v2; sc[mt][nt][3] = v3;
                mx0 = fmaxf(mx0, fmaxf(v0, v1));
                mx1 = fmaxf(mx1, fmaxf(v2, v3));
            }
            mx0 = fmaxf(mx0, __shfl_xor_sync(0xffffffffu, mx0, 1));
            mx0 = fmaxf(mx0, __shfl_xor_sync(0xffffffffu, mx0, 2));
            mx1 = fmaxf(mx1, __shfl_xor_sync(0xffffffffu, mx1, 1));
            mx1 = fmaxf(mx1, __shfl_xor_sync(0xffffffffu, mx1, 2));

            float mn0 = fmaxf(mrow[mt][0], mx0), mn1 = fmaxf(mrow[mt][1], mx1);
            float s0 = __expf(mrow[mt][0] - mn0), s1 = __expf(mrow[mt][1] - mn1);
            mrow[mt][0] = mn0; mrow[mt][1] = mn1;

            int wr = wrow + 16 * mt;
            float sum0 = 0.f, sum1 = 0.f;
            #pragma unroll
            for (int nt = 0; nt < 8; nt++) {
                float p0 = __expf(sc[mt][nt][0] - mn0);
                float p1 = __expf(sc[mt][nt][1] - mn0);
                float p2 = __expf(sc[mt][nt][2] - mn1);
                float p3 = __expf(sc[mt][nt][3] - mn1);
                sum0 += p0 + p1; sum1 += p2 + p3;
                *(float2*)&Ps[(wr + g)     * SK + 8*nt + 2*t] =
                    make_float2(rnd_tf32(p0), rnd_tf32(p1));
                *(float2*)&Ps[(wr + g + 8) * SK + 8*nt + 2*t] =
                    make_float2(rnd_tf32(p2), rnd_tf32(p3));
            }
            sum0 += __shfl_xor_sync(0xffffffffu, sum0, 1);
            sum0 += __shfl_xor_sync(0xffffffffu, sum0, 2);
            sum1 += __shfl_xor_sync(0xffffffffu, sum1, 1);
            sum1 += __shfl_xor_sync(0xffffffffu, sum1, 2);
            lrow[mt][0] = lrow[mt][0] * s0 + sum0;
            lrow[mt][1] = lrow[mt][1] * s1 + sum1;

            #pragma unroll
            for (int nt = 0; nt < 8; nt++) {
                o[mt][nt][0] *= s0; o[mt][nt][1] *= s0;
                o[mt][nt][2] *= s1; o[mt][nt][3] *= s1;
            }
        }
        __syncwarp();                          // P visible within warp

        // ---- O += P @ V: V fragments reused across both m-tiles
        #pragma unroll
        for (int ks = 0; ks < 8; ks++) {
            unsigned pa[2][4];
            #pragma unroll
            for (int mt = 0; mt < 2; mt++) {
                int wr = wrow + 16 * mt;
                pa[mt][0] = __float_as_uint(Ps[(wr + g)     * SK + 8*ks + t]);
                pa[mt][1] = __float_as_uint(Ps[(wr + g + 8) * SK + 8*ks + t]);
                pa[mt][2] = __float_as_uint(Ps[(wr + g)     * SK + 8*ks + t + 4]);
                pa[mt][3] = __float_as_uint(Ps[(wr + g + 8) * SK + 8*ks + t + 4]);
            }
            #pragma unroll
            for (int nt = 0; nt < 8; nt++) {
                unsigned bb[2];
                bb[0] = __float_as_uint(Vs[(8*ks + t)     * SV + 8*nt + g]);
                bb[1] = __float_as_uint(Vs[(8*ks + t + 4) * SV + 8*nt + g]);
                mma_tf32(o[0][nt], pa[0], bb);
                mma_tf32(o[1][nt], pa[1], bb);
            }
        }
    }

    // ---- epilogue: O / l, tf32-rounded (feeds O-proj GEMM)
    #pragma unroll
    for (int mt = 0; mt < 2; mt++) {
        float inv0 = __fdividef(1.f, lrow[mt][0]);
        float inv1 = __fdividef(1.f, lrow[mt][1]);
        #pragma unroll
        for (int nt = 0; nt < 8; nt++) {
            *(float2*)&cb[(size_t)rown[mt][0] * D_ + 8*nt + 2*t] =
                make_float2(rnd_tf32(o[mt][nt][0] * inv0), rnd_tf32(o[mt][nt][1] * inv0));
            *(float2*)&cb[(size_t)rown[mt][1] * D_ + 8*nt + 2*t] =
                make_float2(rnd_tf32(o[mt][nt][2] * inv1), rnd_tf32(o[mt][nt][3] * inv1));
        }
    }
}

// ---------------- launcher -------------------------------------------------------
extern "C" void kernel_launch(void* const* d_in, const int* in_sizes, int n_in,
                              void* d_out, int out_size)
{
    const float* x     = (const float*)d_in[0];
    const float* ln1_s = (const float*)d_in[1];
    const float* ln1_b = (const float*)d_in[2];
    const float* wq    = (const float*)d_in[3];
    const float* wk    = (const float*)d_in[4];
    const float* wv    = (const float*)d_in[5];
    const float* wo    = (const float*)d_in[6];
    const float* bo    = (const float*)d_in[7];
    const float* ln2_s = (const float*)d_in[8];
    const float* ln2_b = (const float*)d_in[9];
    const float* w1    = (const float*)d_in[10];
    const float* b1    = (const float*)d_in[11];
    const float* w2    = (const float*)d_in[12];
    const float* b2    = (const float*)d_in[13];
    float* out = (float*)d_out;

    float *ln, *qkv, *ctx, *h, *ffn, *pool;
    cudaGetSymbolAddress((void**)&ln,   g_ln);
    cudaGetSymbolAddress((void**)&qkv,  g_qkv);
    cudaGetSymbolAddress((void**)&ctx,  g_ctx);
    cudaGetSymbolAddress((void**)&h,    g_h);
    cudaGetSymbolAddress((void**)&ffn,  g_ffn);
    cudaGetSymbolAddress((void**)&pool, g_pool);

    float* wqkvP = pool;            // [1024, 3072]

    cudaFuncSetAttribute(flash_attn_kernel,
                         cudaFuncAttributeMaxDynamicSharedMemorySize, FLASH_SMEM);
    cudaFuncSetAttribute(sgemm_tf32_kernel,
                         cudaFuncAttributeMaxDynamicSharedMemorySize, GEMM_SMEM);

    // 0) weight prep: pack QKV [1024,3072] (rounded). wo/w1/w2 used raw (HW trunc).
    pack_round_kernel<<<1024, 256>>>(wq, wqkvP, 0);
    pack_round_kernel<<<1024, 256>>>(wk, wqkvP, 256);
    pack_round_kernel<<<1024, 256>>>(wv, wqkvP, 512);

    // 1) ln1(x)
    ln_kernel<<<M_, 256>>>(x, ln1_s, ln1_b, ln);

    // 2) fused QKV projection (one GEMM, N=3072), output tf32-rounded
    dim3 gqkv(QKVD / 128, M_ / 128);
    sgemm_tf32_kernel<<<gqkv, 128, GEMM_SMEM>>>(ln, wqkvP, nullptr, nullptr, qkv,
                                                M_, QKVD, D_, 0, 1);

    // 3) fused flash attention -> ctx (tf32-rounded)
    flash_attn_kernel<<<dim3(S_/128, B_*H_), 128, FLASH_SMEM>>>(qkv, ctx);

    // 4) output projection + bias + residual -> h (raw wo)
    dim3 gp(D_ / 128, M_ / 128);
    sgemm_tf32_kernel<<<gp, 128, GEMM_SMEM>>>(ctx, wo, bo, x, h, M_, D_, D_, 0, 0);

    // 5) ln2(h)
    ln_kernel<<<M_, 256>>>(h, ln2_s, ln2_b, ln);

    // 6) FFN (raw w1/w2)
    dim3 gf1(DFF_ / 128, M_ / 128);
    sgemm_tf32_kernel<<<gf1, 128, GEMM_SMEM>>>(ln, w1, b1, nullptr, ffn, M_, DFF_, D_, 1, 1);
    sgemm_tf32_kernel<<<gp, 128, GEMM_SMEM>>>(ffn, w2, b2, h, out, M_, D_, DFF_, 0, 0);
}

// round 13
// speedup vs baseline: 1.0639x; 1.0639x over previous
#include <cuda_runtime.h>
#include <math.h>
#include <stdint.h>

#define B_   2
#define S_   2048
#define D_   1024
#define H_   16
#define DH_  64
#define DFF_ 4096
#define M_   (B_*S_)    // 4096 tokens
#define QKVD 3072

// ---------------- scratch (static device allocations) ---------------------------
__device__ float g_ln [M_ * D_];
__device__ float g_qkv[(size_t)M_ * QKVD];              // 48 MB
__device__ float g_ctx[M_ * D_];
__device__ float g_h  [M_ * D_];
__device__ float g_ffn[(size_t)M_ * DFF_];              // 64 MB
__device__ float g_pool[4 * 1024 * 1024];               // packed QKV weights

// ---------------- helpers --------------------------------------------------------
__device__ __forceinline__ unsigned f2tf32(float x) {
    unsigned r;
    asm("cvt.rna.tf32.f32 %0, %1;" : "=r"(r) : "f"(x));
    return r;
}
__device__ __forceinline__ float rnd_tf32(float x) {
    return __uint_as_float(f2tf32(x));
}
__device__ __forceinline__ void mma_tf32(float* c, const unsigned* a, const unsigned* b) {
    asm volatile(
        "mma.sync.aligned.m16n8k8.row.col.f32.tf32.tf32.f32 "
        "{%0,%1,%2,%3}, {%4,%5,%6,%7}, {%8,%9}, {%0,%1,%2,%3};"
        : "+f"(c[0]), "+f"(c[1]), "+f"(c[2]), "+f"(c[3])
        : "r"(a[0]), "r"(a[1]), "r"(a[2]), "r"(a[3]), "r"(b[0]), "r"(b[1]));
}
__device__ __forceinline__ void cpasync16(float* smem, const float* gmem) {
    unsigned s = (unsigned)__cvta_generic_to_shared(smem);
    asm volatile("cp.async.cg.shared.global [%0], [%1], 16;" :: "r"(s), "l"(gmem));
}

// ---------------- weight prep: pack QKV into [1024, 3072] (rounded, free) --------
__global__ void pack_round_kernel(const float* __restrict__ in,
                                  float* __restrict__ out, int off4)
{
    int i = blockIdx.x * 256 + threadIdx.x;     // over 1024*256 float4s
    int k = i >> 8, n4 = i & 255;
    float4 a = ((const float4*)in)[i];
    a.x = rnd_tf32(a.x); a.y = rnd_tf32(a.y);
    a.z = rnd_tf32(a.z); a.w = rnd_tf32(a.w);
    ((float4*)(out + (size_t)k * QKVD))[off4 + n4] = a;
}

// ---------------- LayerNorm: one-pass, float4-per-thread, shuffle reduce ---------
__global__ void ln_kernel(const float* __restrict__ x,
                          const float* __restrict__ sc,
                          const float* __restrict__ sh,
                          float* __restrict__ out)
{
    int row = blockIdx.x;
    const int tid = threadIdx.x;             // 256 threads, D = 1024 = 256*4
    float4 v = *(const float4*)(x + (size_t)row * D_ + tid * 4);

    float s  = v.x + v.y + v.z + v.w;
    float s2 = v.x*v.x + v.y*v.y + v.z*v.z + v.w*v.w;
    #pragma unroll
    for (int o = 16; o > 0; o >>= 1) {
        s  += __shfl_xor_sync(0xffffffffu, s,  o);
        s2 += __shfl_xor_sync(0xffffffffu, s2, o);
    }
    __shared__ float ws[8], ws2[8];
    int warp = tid >> 5, lane = tid & 31;
    if (lane == 0) { ws[warp] = s; ws2[warp] = s2; }
    __syncthreads();
    if (warp == 0) {
        float a  = (lane < 8) ? ws[lane]  : 0.f;
        float a2 = (lane < 8) ? ws2[lane] : 0.f;
        #pragma unroll
        for (int o = 4; o > 0; o >>= 1) {
            a  += __shfl_xor_sync(0xffffffffu, a,  o);
            a2 += __shfl_xor_sync(0xffffffffu, a2, o);
        }
        if (lane == 0) { ws[0] = a; ws2[0] = a2; }
    }
    __syncthreads();

    float mean = ws[0] * (1.0f / D_);
    float var  = ws2[0] * (1.0f / D_) - mean * mean;
    float inv  = rsqrtf(var + 1e-5f);

    float4 g = *(const float4*)(sc + tid * 4);
    float4 bsh = *(const float4*)(sh + tid * 4);
    float4 o4;
    o4.x = rnd_tf32((v.x - mean) * inv * g.x + bsh.x);
    o4.y = rnd_tf32((v.y - mean) * inv * g.y + bsh.y);
    o4.z = rnd_tf32((v.z - mean) * inv * g.z + bsh.z);
    o4.w = rnd_tf32((v.w - mean) * inv * g.w + bsh.w);
    *(float4*)(out + (size_t)row * D_ + tid * 4) = o4;
}

// ---------------- TF32 mma.sync GEMM: 4 warps @ 64x64, 4-stage ring (R11) --------
#define AS_STRIDE 20
#define BS_STRIDE 136
#define AS_BUF (128 * AS_STRIDE)
#define BS_BUF (16 * BS_STRIDE)
#define STG_FLOATS (AS_BUF + BS_BUF)
#define GSTAGES 4
#define GEMM_SMEM (GSTAGES * STG_FLOATS * 4)

__global__ __launch_bounds__(128, 2)
void sgemm_tf32_kernel(const float* __restrict__ A,
                       const float* __restrict__ Bm,
                       const float* __restrict__ bias,   // may be null
                       const float* __restrict__ res,    // may be null
                       float* __restrict__ C,
                       int M, int N, int K, int gelu, int roundOut)
{
    extern __shared__ float sm[];

    const int tid  = threadIdx.x;
    const int lane = tid & 31;
    const int warp = tid >> 5;       // 0..3
    const int g    = lane >> 2;
    const int t    = lane & 3;
    const int warpRow = warp >> 1;
    const int warpCol = warp & 1;

    const int rowBase = blockIdx.y * 128;
    const int colBase = blockIdx.x * 128;

    float acc[4][8][4];
    #pragma unroll
    for (int i = 0; i < 4; i++)
        #pragma unroll
        for (int j = 0; j < 8; j++)
            #pragma unroll
            for (int r = 0; r < 4; r++) acc[i][j][r] = 0.f;

    const int nIter = K / 16;

    #pragma unroll
    for (int p = 0; p < GSTAGES - 1; p++) {
        float* As = sm + p * STG_FLOATS;
        float* Bs = As + AS_BUF;
        int k0 = p * 16;
        #pragma unroll
        for (int u = 0; u < 4; u++) {
            int idx = u * 128 + tid;
            int ar = idx >> 2, ac = (idx & 3) * 4;
            cpasync16(&As[ar * AS_STRIDE + ac], &A[(size_t)(rowBase + ar) * K + k0 + ac]);
            int br = idx >> 5, bc = (idx & 31) * 4;
            cpasync16(&Bs[br * BS_STRIDE + bc], &Bm[(size_t)(k0 + br) * N + colBase + bc]);
        }
        asm volatile("cp.async.commit_group;");
    }

    for (int kt = 0; kt < nIter; ++kt) {
        if (kt + 3 <= nIter)      { asm volatile("cp.async.wait_group 2;"); }
        else if (kt + 2 == nIter) { asm volatile("cp.async.wait_group 1;"); }
        else                      { asm volatile("cp.async.wait_group 0;"); }
        __syncthreads();

        if (kt + 3 < nIter) {
            float* As = sm + ((kt + 3) & 3) * STG_FLOATS;
            float* Bs = As + AS_BUF;
            int k0 = (kt + 3) * 16;
            #pragma unroll
            for (int u = 0; u < 4; u++) {
                int idx = u * 128 + tid;
                int ar = idx >> 2, ac = (idx & 3) * 4;
                cpasync16(&As[ar * AS_STRIDE + ac], &A[(size_t)(rowBase + ar) * K + k0 + ac]);
                int br = idx >> 5, bc = (idx & 31) * 4;
                cpasync16(&Bs[br * BS_STRIDE + bc], &Bm[(size_t)(k0 + br) * N + colBase + bc]);
            }
            asm volatile("cp.async.commit_group;");
        }

        const float* As_ = sm + (kt & 3) * STG_FLOATS;
        const float* Bs_ = As_ + AS_BUF;

        #pragma unroll
        for (int ks = 0; ks < 2; ks++) {
            const int k = ks * 8;
            unsigned afr[4][4], bfr[8][2];
            #pragma unroll
            for (int mt = 0; mt < 4; mt++) {
                int m = warpRow * 64 + mt * 16 + g;
                afr[mt][0] = __float_as_uint(As_[m * AS_STRIDE + k + t]);
                afr[mt][1] = __float_as_uint(As_[(m + 8) * AS_STRIDE + k + t]);
                afr[mt][2] = __float_as_uint(As_[m * AS_STRIDE + k + t + 4]);
                afr[mt][3] = __float_as_uint(As_[(m + 8) * AS_STRIDE + k + t + 4]);
            }
            #pragma unroll
            for (int nt = 0; nt < 8; nt++) {
                int n = warpCol * 64 + nt * 8 + g;
                bfr[nt][0] = __float_as_uint(Bs_[(k + t) * BS_STRIDE + n]);
                bfr[nt][1] = __float_as_uint(Bs_[(k + t + 4) * BS_STRIDE + n]);
            }
            #pragma unroll
            for (int mt = 0; mt < 4; mt++)
                #pragma unroll
                for (int nt = 0; nt < 8; nt++)
                    mma_tf32(acc[mt][nt], afr[mt], bfr[nt]);
        }
    }

    #pragma unroll
    for (int mt = 0; mt < 4; mt++) {
        #pragma unroll
        for (int nt = 0; nt < 8; nt++) {
            int r0 = rowBase + warpRow * 64 + mt * 16 + g;
            int c0 = colBase + warpCol * 64 + nt * 8 + 2 * t;
            #pragma unroll
            for (int half = 0; half < 2; half++) {
                int r = r0 + half * 8;
                float v0 = acc[mt][nt][2*half], v1 = acc[mt][nt][2*half+1];
                if (bias) { v0 += bias[c0]; v1 += bias[c0 + 1]; }
                if (gelu) {
                    float t0 = 1.5957691216057308f * v0 + 0.0713548162726009f * v0 * v0 * v0;
                    v0 = __fdividef(v0, 1.f + __expf(-t0));
                    float t1 = 1.5957691216057308f * v1 + 0.0713548162726009f * v1 * v1 * v1;
                    v1 = __fdividef(v1, 1.f + __expf(-t1));
                }
                if (res) {
                    float2 rr = *(const float2*)&res[(size_t)r * N + c0];
                    v0 += rr.x; v1 += rr.y;
                }
                if (roundOut) { v0 = rnd_tf32(v0); v1 = rnd_tf32(v1); }
                *(float2*)&C[(size_t)r * N + c0] = make_float2(v0, v1);
            }
        }
    }
}

// ---------------- fused flash attention: 4 warps, 32 q-rows/warp (R11 winner) ----
#define SK 68
#define SV 72
#define KVBUF (64*SK + 64*SV)
#define FLASH_SMEM ((128*SK + 2*KVBUF) * 4)

__global__ __launch_bounds__(128)
void flash_attn_kernel(const float* __restrict__ qkv, float* __restrict__ ctx)
{
    extern __shared__ float sm[];
    float* Ps = sm;                       // 128 x SK (Q prologue, then P)
    float* KV0 = sm + 128 * SK;           // double-buffered K/V tiles

    const int qt = (int)(gridDim.x - 1) - (int)blockIdx.x;   // big tiles first
    const int bh = blockIdx.y;
    const int b = bh >> 4, h = bh & 15;
    const float* qb = qkv + (size_t)b * S_ * QKVD + h * DH_;
    const float* kb = qb + D_;
    const float* vb = qb + 2 * D_;
    float* cb = ctx + (size_t)b * S_ * D_ + h * DH_;

    const int tid = threadIdx.x, lane = tid & 31, warp = tid >> 5;   // warp 0..3
    const int g = lane >> 2, t = lane & 3;
    const int rowBase = qt * 128;
    const int wrow = warp * 32;            // 32 q-rows per warp
    const int ktmax = 2 * qt + 2;

    // ---- Q prologue: each warp stages its own 32 rows
    #pragma unroll
    for (int u = 0; u < 16; u++) {
        int idx = u * 32 + lane;
        int r = idx >> 4, c4 = (idx & 15) * 4;
        cpasync16(&Ps[(wrow + r) * SK + c4],
                  &qb[(size_t)(rowBase + wrow + r) * QKVD + c4]);
    }
    asm volatile("cp.async.commit_group;");
    asm volatile("cp.async.wait_group 0;");
    __syncwarp();

    unsigned qa[2][8][4];
    #pragma unroll
    for (int mt = 0; mt < 2; mt++) {
        int wr = wrow + 16 * mt;
        #pragma unroll
        for (int ks = 0; ks < 8; ks++) {
            qa[mt][ks][0] = __float_as_uint(0.125f * Ps[(wr + g)     * SK + 8*ks + t]);
            qa[mt][ks][1] = __float_as_uint(0.125f * Ps[(wr + g + 8) * SK + 8*ks + t]);
            qa[mt][ks][2] = __float_as_uint(0.125f * Ps[(wr + g)     * SK + 8*ks + t + 4]);
            qa[mt][ks][3] = __float_as_uint(0.125f * Ps[(wr + g + 8) * SK + 8*ks + t + 4]);
        }
    }

    // ---- prefetch KV tile 0 into buffer 0
    {
        float* Ks = KV0;
        float* Vs = KV0 + 64 * SK;
        #pragma unroll
        for (int u = 0; u < 8; u++) {
            int idx = u * 128 + tid;
            int r = idx >> 4, c4 = (idx & 15) * 4;
            cpasync16(&Ks[r * SK + c4], &kb[(size_t)r * QKVD + c4]);
            cpasync16(&Vs[r * SV + c4], &vb[(size_t)r * QKVD + c4]);
        }
        asm volatile("cp.async.commit_group;");
    }

    float o[2][8][4];
    #pragma unroll
    for (int mt = 0; mt < 2; mt++)
        #pragma unroll
        for (int nt = 0; nt < 8; nt++)
            #pragma unroll
            for (int e = 0; e < 4; e++) o[mt][nt][e] = 0.f;
    float mrow[2][2] = { {-1e30f, -1e30f}, {-1e30f, -1e30f} };
    float lrow[2][2] = { {0.f, 0.f}, {0.f, 0.f} };
    int rown[2][2];
    #pragma unroll
    for (int mt = 0; mt < 2; mt++) {
        rown[mt][0] = rowBase + wrow + 16 * mt + g;
        rown[mt][1] = rown[mt][0] + 8;
    }

    for (int kt = 0; kt < ktmax; kt++) {
        __syncthreads();                       // prev compute done on buf^1
        if (kt + 1 < ktmax) {                  // prefetch next tile into buf^1
            float* Ks = KV0 + ((kt + 1) & 1) * KVBUF;
            float* Vs = Ks + 64 * SK;
            #pragma unroll
            for (int u = 0; u < 8; u++) {
                int idx = u * 128 + tid;
                int r = idx >> 4, c4 = (idx & 15) * 4;
                cpasync16(&Ks[r * SK + c4], &kb[(size_t)((kt + 1) * 64 + r) * QKVD + c4]);
                cpasync16(&Vs[r * SV + c4], &vb[(size_t)((kt + 1) * 64 + r) * QKVD + c4]);
            }
            asm volatile("cp.async.commit_group;");
            asm volatile("cp.async.wait_group 1;");
        } else {
            asm volatile("cp.async.wait_group 0;");
        }
        __syncthreads();                       // tile kt visible to all

        const float* Ks = KV0 + (kt & 1) * KVBUF;
        const float* Vs = Ks + 64 * SK;

        // ---- S = Q K^T: each K fragment reused across both m-tiles
        float sc[2][8][4];
        #pragma unroll
        for (int mt = 0; mt < 2; mt++)
            #pragma unroll
            for (int nt = 0; nt < 8; nt++)
                sc[mt][nt][0] = sc[mt][nt][1] = sc[mt][nt][2] = sc[mt][nt][3] = 0.f;
        #pragma unroll
        for (int nt = 0; nt < 8; nt++) {
            #pragma unroll
            for (int ks = 0; ks < 8; ks++) {
                unsigned bb[2];
                bb[0] = __float_as_uint(Ks[(8*nt + g) * SK + 8*ks + t]);
                bb[1] = __float_as_uint(Ks[(8*nt + g) * SK + 8*ks + t + 4]);
                mma_tf32(sc[0][nt], qa[0][ks], bb);
                mma_tf32(sc[1][nt], qa[1][ks], bb);
            }
        }

        // ---- mask + online softmax (per m-tile)
        const int colb = kt * 64 + 2 * t;
        #pragma unroll
        for (int mt = 0; mt < 2; mt++) {
            float mx0 = -1e30f, mx1 = -1e30f;
            #pragma unroll
            for (int nt = 0; nt < 8; nt++) {
                int c0 = colb + 8 * nt;
                float v0 = sc[mt][nt][0]; if (c0     > rown[mt][0]) v0 = -1e30f;
                float v1 = sc[mt][nt][1]; if (c0 + 1 > rown[mt][0]) v1 = -1e30f;
                float v2 = sc[mt][nt][2]; if (c0     > rown[mt][1]) v2 = -1e30f;
                float v3 = sc[mt][nt][3]; if (c0 + 1 > rown[mt][1]) v3 = -1e30f;
                sc[mt][nt][0] = v0; sc[mt][nt][1] = v1;
                sc[mt][nt][2] = v2; sc[mt][nt][3] = v3;
                mx0 = fmaxf(mx0, fmaxf(v0, v1));
                mx1 = fmaxf(mx1, fmaxf(v2, v3));
            }
            mx0 = fmaxf(mx0, __shfl_xor_sync(0xffffffffu, mx0, 1));
            mx0 = fmaxf(mx0, __shfl_xor_sync(0xffffffffu, mx0, 2));
            mx1 = fmaxf(mx1, __shfl_xor_sync(0xffffffffu, mx1, 1));
            mx1 = fmaxf(mx1, __shfl_xor_sync(0xffffffffu, mx1, 2));

            float mn0 = fmaxf(mrow[mt][0], mx0), mn1 = fmaxf(mrow[mt][1], mx1);
            float s0 = __expf(mrow[mt][0] - mn0), s1 = __expf(mrow[mt][1] - mn1);
            mrow[mt][0] = mn0; mrow[mt][1] = mn1;

            int wr = wrow + 16 * mt;
            float sum0 = 0.f, sum1 = 0.f;
            #pragma unroll
            for (int nt = 0; nt < 8; nt++) {
                float p0 = __expf(sc[mt][nt][0] - mn0);
                float p1 = __expf(sc[mt][nt][1] - mn0);
                float p2 = __expf(sc[mt][nt][2] - mn1);
                float p3 = __expf(sc[mt][nt][3] - mn1);
                sum0 += p0 + p1; sum1 += p2 + p3;
                *(float2*)&Ps[(wr + g)     * SK + 8*nt + 2*t] =
                    make_float2(rnd_tf32(p0), rnd_tf32(p1));
                *(float2*)&Ps[(wr + g + 8) * SK + 8*nt + 2*t] =
                    make_float2(rnd_tf32(p2), rnd_tf32(p3));
            }
            sum0 += __shfl_xor_sync(0xffffffffu, sum0, 1);
            sum0 += __shfl_xor_sync(0xffffffffu, sum0, 2);
            sum1 += __shfl_xor_sync(0xffffffffu, sum1, 1);
            sum1 += __shfl_xor_sync(0xffffffffu, sum1, 2);
            lrow[mt][0] = lrow[mt][0] * s0 + sum0;
            lrow[mt][1] = lrow[mt][1] * s1 + sum1;

            #pragma unroll
            for (int nt = 0; nt < 8; nt++) {
                o[mt][nt][0] *= s0; o[mt][nt][1] *= s0;
                o[mt][nt][2] *= s1; o[mt][nt][3] *= s1;
            }
        }
        __syncwarp();                          // P visible within warp

        // ---- O += P @ V: V fragments reused across both m-tiles
        #pragma unroll
        for (int ks = 0; ks < 8; ks++) {
            unsigned pa[2][4];
            #pragma unroll
            for (int mt = 0; mt < 2; mt++) {
                int wr = wrow + 16 * mt;
                pa[mt][0] = __float_as_uint(Ps[(wr + g)     * SK + 8*ks + t]);
                pa[mt][1] = __float_as_uint(Ps[(wr + g + 8) * SK + 8*ks + t]);
                pa[mt][2] = __float_as_uint(Ps[(wr + g)     * SK + 8*ks + t + 4]);
                pa[mt][3] = __float_as_uint(Ps[(wr + g + 8) * SK + 8*ks + t + 4]);
            }
            #pragma unroll
            for (int nt = 0; nt < 8; nt++) {
                unsigned bb[2];
                bb[0] = __float_as_uint(Vs[(8*ks + t)     * SV + 8*nt + g]);
                bb[1] = __float_as_uint(Vs[(8*ks + t + 4) * SV + 8*nt + g]);
                mma_tf32(o[0][nt], pa[0], bb);
                mma_tf32(o[1][nt], pa[1], bb);
            }
        }
    }

    // ---- epilogue: O / l, tf32-rounded (feeds O-proj GEMM)
    #pragma unroll
    for (int mt = 0; mt < 2; mt++) {
        float inv0 = __fdividef(1.f, lrow[mt][0]);
        float inv1 = __fdividef(1.f, lrow[mt][1]);
        #pragma unroll
        for (int nt = 0; nt < 8; nt++) {
            *(float2*)&cb[(size_t)rown[mt][0] * D_ + 8*nt + 2*t] =
                make_float2(rnd_tf32(o[mt][nt][0] * inv0), rnd_tf32(o[mt][nt][1] * inv0));
            *(float2*)&cb[(size_t)rown[mt][1] * D_ + 8*nt + 2*t] =
                make_float2(rnd_tf32(o[mt][nt][2] * inv1), rnd_tf32(o[mt][nt][3] * inv1));
        }
    }
}

// ---------------- launcher -------------------------------------------------------
extern "C" void kernel_launch(void* const* d_in, const int* in_sizes, int n_in,
                              void* d_out, int out_size)
{
    const float* x     = (const float*)d_in[0];
    const float* ln1_s = (const float*)d_in[1];
    const float* ln1_b = (const float*)d_in[2];
    const float* wq    = (const float*)d_in[3];
    const float* wk    = (const float*)d_in[4];
    const float* wv    = (const float*)d_in[5];
    const float* wo    = (const float*)d_in[6];
    const float* bo    = (const float*)d_in[7];
    const float* ln2_s = (const float*)d_in[8];
    const float* ln2_b = (const float*)d_in[9];
    const float* w1    = (const float*)d_in[10];
    const float* b1    = (const float*)d_in[11];
    const float* w2    = (const float*)d_in[12];
    const float* b2    = (const float*)d_in[13];
    float* out = (float*)d_out;

    float *ln, *qkv, *ctx, *h, *ffn, *pool;
    cudaGetSymbolAddress((void**)&ln,   g_ln);
    cudaGetSymbolAddress((void**)&qkv,  g_qkv);
    cudaGetSymbolAddress((void**)&ctx,  g_ctx);
    cudaGetSymbolAddress((void**)&h,    g_h);
    cudaGetSymbolAddress((void**)&ffn,  g_ffn);
    cudaGetSymbolAddress((void**)&pool, g_pool);

    float* wqkvP = pool;            // [1024, 3072]

    cudaFuncSetAttribute(flash_attn_kernel,
                         cudaFuncAttributeMaxDynamicSharedMemorySize, FLASH_SMEM);
    cudaFuncSetAttribute(sgemm_tf32_kernel,
                         cudaFuncAttributeMaxDynamicSharedMemorySize, GEMM_SMEM);

    // 0) weight prep: pack QKV [1024,3072] (rounded). wo/w1/w2 used raw (HW trunc).
    pack_round_kernel<<<1024, 256>>>(wq, wqkvP, 0);
    pack_round_kernel<<<1024, 256>>>(wk, wqkvP, 256);
    pack_round_kernel<<<1024, 256>>>(wv, wqkvP, 512);

    // 1) ln1(x)
    ln_kernel<<<M_, 256>>>(x, ln1_s, ln1_b, ln);

    // 2) fused QKV projection (one GEMM, N=3072), output tf32-rounded
    dim3 gqkv(QKVD / 128, M_ / 128);
    sgemm_tf32_kernel<<<gqkv, 128, GEMM_SMEM>>>(ln, wqkvP, nullptr, nullptr, qkv,
                                                M_, QKVD, D_, 0, 1);

    // 3) fused flash attention -> ctx (tf32-rounded)
    flash_attn_kernel<<<dim3(S_/128, B_*H_), 128, FLASH_SMEM>>>(qkv, ctx);

    // 4) output projection + bias + residual -> h (raw wo)
    dim3 gp(D_ / 128, M_ / 128);
    sgemm_tf32_kernel<<<gp, 128, GEMM_SMEM>>>(ctx, wo, bo, x, h, M_, D_, D_, 0, 0);

    // 5) ln2(h)
    ln_kernel<<<M_, 256>>>(h, ln2_s, ln2_b, ln);

    // 6) FFN (raw w1/w2)
    dim3 gf1(DFF_ / 128, M_ / 128);
    sgemm_tf32_kernel<<<gf1, 128, GEMM_SMEM>>>(ln, w1, b1, nullptr, ffn, M_, DFF_, D_, 1, 1);
    sgemm_tf32_kernel<<<gp, 128, GEMM_SMEM>>>(ffn, w2, b2, h, out, M_, D_, DFF_, 0, 0);
}

// round 14
// speedup vs baseline: 1.0729x; 1.0085x over previous
#include <cuda_runtime.h>
#include <math.h>
#include <stdint.h>

#define B_   2
#define S_   2048
#define D_   1024
#define H_   16
#define DH_  64
#define DFF_ 4096
#define M_   (B_*S_)    // 4096 tokens
#define QKVD 3072

// ---------------- scratch (static device allocations) ---------------------------
__device__ float g_ln [M_ * D_];
__device__ float g_qkv[(size_t)M_ * QKVD];              // 48 MB
__device__ float g_ctx[M_ * D_];
__device__ float g_h  [M_ * D_];
__device__ float g_ffn[(size_t)M_ * DFF_];              // 64 MB
__device__ float g_pool[4 * 1024 * 1024];               // packed QKV weights

// ---------------- helpers --------------------------------------------------------
__device__ __forceinline__ unsigned f2tf32(float x) {
    unsigned r;
    asm("cvt.rna.tf32.f32 %0, %1;" : "=r"(r) : "f"(x));
    return r;
}
__device__ __forceinline__ float rnd_tf32(float x) {
    return __uint_as_float(f2tf32(x));
}
__device__ __forceinline__ void mma_tf32(float* c, const unsigned* a, const unsigned* b) {
    asm volatile(
        "mma.sync.aligned.m16n8k8.row.col.f32.tf32.tf32.f32 "
        "{%0,%1,%2,%3}, {%4,%5,%6,%7}, {%8,%9}, {%0,%1,%2,%3};"
        : "+f"(c[0]), "+f"(c[1]), "+f"(c[2]), "+f"(c[3])
        : "r"(a[0]), "r"(a[1]), "r"(a[2]), "r"(a[3]), "r"(b[0]), "r"(b[1]));
}
__device__ __forceinline__ void cpasync16(float* smem, const float* gmem) {
    unsigned s = (unsigned)__cvta_generic_to_shared(smem);
    asm volatile("cp.async.cg.shared.global [%0], [%1], 16;" :: "r"(s), "l"(gmem));
}

// ---------------- weight prep: pack Q,K,V into [1024, 3072] in ONE launch --------
__global__ void pack_qkv_kernel(const float* __restrict__ wq,
                                const float* __restrict__ wk,
                                const float* __restrict__ wv,
                                float* __restrict__ out)
{
    int which = blockIdx.x >> 10;               // 0..2
    int blk   = blockIdx.x & 1023;
    const float* in = (which == 0) ? wq : (which == 1) ? wk : wv;
    int off4 = which * 256;

    int i = blk * 256 + threadIdx.x;            // over 1024*256 float4s
    int k = i >> 8, n4 = i & 255;
    float4 a = ((const float4*)in)[i];
    a.x = rnd_tf32(a.x); a.y = rnd_tf32(a.y);
    a.z = rnd_tf32(a.z); a.w = rnd_tf32(a.w);
    ((float4*)(out + (size_t)k * QKVD))[off4 + n4] = a;
}

// ---------------- LayerNorm: one-pass, float4-per-thread, shuffle reduce ---------
__global__ void ln_kernel(const float* __restrict__ x,
                          const float* __restrict__ sc,
                          const float* __restrict__ sh,
                          float* __restrict__ out)
{
    int row = blockIdx.x;
    const int tid = threadIdx.x;             // 256 threads, D = 1024 = 256*4
    float4 v = *(const float4*)(x + (size_t)row * D_ + tid * 4);

    float s  = v.x + v.y + v.z + v.w;
    float s2 = v.x*v.x + v.y*v.y + v.z*v.z + v.w*v.w;
    #pragma unroll
    for (int o = 16; o > 0; o >>= 1) {
        s  += __shfl_xor_sync(0xffffffffu, s,  o);
        s2 += __shfl_xor_sync(0xffffffffu, s2, o);
    }
    __shared__ float ws[8], ws2[8];
    int warp = tid >> 5, lane = tid & 31;
    if (lane == 0) { ws[warp] = s; ws2[warp] = s2; }
    __syncthreads();
    if (warp == 0) {
        float a  = (lane < 8) ? ws[lane]  : 0.f;
        float a2 = (lane < 8) ? ws2[lane] : 0.f;
        #pragma unroll
        for (int o = 4; o > 0; o >>= 1) {
            a  += __shfl_xor_sync(0xffffffffu, a,  o);
            a2 += __shfl_xor_sync(0xffffffffu, a2, o);
        }
        if (lane == 0) { ws[0] = a; ws2[0] = a2; }
    }
    __syncthreads();

    float mean = ws[0] * (1.0f / D_);
    float var  = ws2[0] * (1.0f / D_) - mean * mean;
    float inv  = rsqrtf(var + 1e-5f);

    float4 g = *(const float4*)(sc + tid * 4);
    float4 bsh = *(const float4*)(sh + tid * 4);
    float4 o4;
    o4.x = rnd_tf32((v.x - mean) * inv * g.x + bsh.x);
    o4.y = rnd_tf32((v.y - mean) * inv * g.y + bsh.y);
    o4.z = rnd_tf32((v.z - mean) * inv * g.z + bsh.z);
    o4.w = rnd_tf32((v.w - mean) * inv * g.w + bsh.w);
    *(float4*)(out + (size_t)row * D_ + tid * 4) = o4;
}

// ---------------- TF32 mma.sync GEMM: 4 warps @ 64x64, 5-stage ring --------------
#define AS_STRIDE 20
#define BS_STRIDE 136
#define AS_BUF (128 * AS_STRIDE)
#define BS_BUF (16 * BS_STRIDE)
#define STG_FLOATS (AS_BUF + BS_BUF)
#define GSTAGES 5
#define GEMM_SMEM (GSTAGES * STG_FLOATS * 4)   // 94720 B

__global__ __launch_bounds__(128, 2)
void sgemm_tf32_kernel(const float* __restrict__ A,
                       const float* __restrict__ Bm,
                       const float* __restrict__ bias,   // may be null
                       const float* __restrict__ res,    // may be null
                       float* __restrict__ C,
                       int M, int N, int K, int gelu, int roundOut)
{
    extern __shared__ float sm[];

    const int tid  = threadIdx.x;
    const int lane = tid & 31;
    const int warp = tid >> 5;       // 0..3
    const int g    = lane >> 2;
    const int t    = lane & 3;
    const int warpRow = warp >> 1;
    const int warpCol = warp & 1;

    const int rowBase = blockIdx.y * 128;
    const int colBase = blockIdx.x * 128;

    float acc[4][8][4];
    #pragma unroll
    for (int i = 0; i < 4; i++)
        #pragma unroll
        for (int j = 0; j < 8; j++)
            #pragma unroll
            for (int r = 0; r < 4; r++) acc[i][j][r] = 0.f;

    const int nIter = K / 16;

    // prologue: fill stages 0..3
    #pragma unroll
    for (int p = 0; p < GSTAGES - 1; p++) {
        float* As = sm + p * STG_FLOATS;
        float* Bs = As + AS_BUF;
        int k0 = p * 16;
        #pragma unroll
        for (int u = 0; u < 4; u++) {
            int idx = u * 128 + tid;
            int ar = idx >> 2, ac = (idx & 3) * 4;
            cpasync16(&As[ar * AS_STRIDE + ac], &A[(size_t)(rowBase + ar) * K + k0 + ac]);
            int br = idx >> 5, bc = (idx & 31) * 4;
            cpasync16(&Bs[br * BS_STRIDE + bc], &Bm[(size_t)(k0 + br) * N + colBase + bc]);
        }
        asm volatile("cp.async.commit_group;");
    }

    int sr = 0;                        // read stage
    int swr = GSTAGES - 1;             // write stage (for kt+4)
    for (int kt = 0; kt < nIter; ++kt) {
        if (kt + 4 <= nIter)      { asm volatile("cp.async.wait_group 3;"); }
        else if (kt + 3 == nIter) { asm volatile("cp.async.wait_group 2;"); }
        else if (kt + 2 == nIter) { asm volatile("cp.async.wait_group 1;"); }
        else                      { asm volatile("cp.async.wait_group 0;"); }
        __syncthreads();

        if (kt + 4 < nIter) {
            float* As = sm + swr * STG_FLOATS;
            float* Bs = As + AS_BUF;
            int k0 = (kt + 4) * 16;
            #pragma unroll
            for (int u = 0; u < 4; u++) {
                int idx = u * 128 + tid;
                int ar = idx >> 2, ac = (idx & 3) * 4;
                cpasync16(&As[ar * AS_STRIDE + ac], &A[(size_t)(rowBase + ar) * K + k0 + ac]);
                int br = idx >> 5, bc = (idx & 31) * 4;
                cpasync16(&Bs[br * BS_STRIDE + bc], &Bm[(size_t)(k0 + br) * N + colBase + bc]);
            }
            asm volatile("cp.async.commit_group;");
        }
        swr = (swr + 1 == GSTAGES) ? 0 : swr + 1;

        const float* As_ = sm + sr * STG_FLOATS;
        const float* Bs_ = As_ + AS_BUF;
        sr = (sr + 1 == GSTAGES) ? 0 : sr + 1;

        #pragma unroll
        for (int ks = 0; ks < 2; ks++) {
            const int k = ks * 8;
            unsigned afr[4][4], bfr[8][2];
            #pragma unroll
            for (int mt = 0; mt < 4; mt++) {
                int m = warpRow * 64 + mt * 16 + g;
                afr[mt][0] = __float_as_uint(As_[m * AS_STRIDE + k + t]);
                afr[mt][1] = __float_as_uint(As_[(m + 8) * AS_STRIDE + k + t]);
                afr[mt][2] = __float_as_uint(As_[m * AS_STRIDE + k + t + 4]);
                afr[mt][3] = __float_as_uint(As_[(m + 8) * AS_STRIDE + k + t + 4]);
            }
            #pragma unroll
            for (int nt = 0; nt < 8; nt++) {
                int n = warpCol * 64 + nt * 8 + g;
                bfr[nt][0] = __float_as_uint(Bs_[(k + t) * BS_STRIDE + n]);
                bfr[nt][1] = __float_as_uint(Bs_[(k + t + 4) * BS_STRIDE + n]);
            }
            #pragma unroll
            for (int mt = 0; mt < 4; mt++)
                #pragma unroll
                for (int nt = 0; nt < 8; nt++)
                    mma_tf32(acc[mt][nt], afr[mt], bfr[nt]);
        }
    }

    #pragma unroll
    for (int mt = 0; mt < 4; mt++) {
        #pragma unroll
        for (int nt = 0; nt < 8; nt++) {
            int r0 = rowBase + warpRow * 64 + mt * 16 + g;
            int c0 = colBase + warpCol * 64 + nt * 8 + 2 * t;
            #pragma unroll
            for (int half = 0; half < 2; half++) {
                int r = r0 + half * 8;
                float v0 = acc[mt][nt][2*half], v1 = acc[mt][nt][2*half+1];
                if (bias) { v0 += bias[c0]; v1 += bias[c0 + 1]; }
                if (gelu) {
                    float t0 = 1.5957691216057308f * v0 + 0.0713548162726009f * v0 * v0 * v0;
                    v0 = __fdividef(v0, 1.f + __expf(-t0));
                    float t1 = 1.5957691216057308f * v1 + 0.0713548162726009f * v1 * v1 * v1;
                    v1 = __fdividef(v1, 1.f + __expf(-t1));
                }
                if (res) {
                    float2 rr = *(const float2*)&res[(size_t)r * N + c0];
                    v0 += rr.x; v1 += rr.y;
                }
                if (roundOut) { v0 = rnd_tf32(v0); v1 = rnd_tf32(v1); }
                *(float2*)&C[(size_t)r * N + c0] = make_float2(v0, v1);
            }
        }
    }
}

// ---------------- fused flash attention: 4 warps, 32 q-rows/warp (R11 winner) ----
#define SK 68
#define SV 72
#define KVBUF (64*SK + 64*SV)
#define FLASH_SMEM ((128*SK + 2*KVBUF) * 4)

__global__ __launch_bounds__(128)
void flash_attn_kernel(const float* __restrict__ qkv, float* __restrict__ ctx)
{
    extern __shared__ float sm[];
    float* Ps = sm;                       // 128 x SK (Q prologue, then P)
    float* KV0 = sm + 128 * SK;           // double-buffered K/V tiles

    const int qt = (int)(gridDim.x - 1) - (int)blockIdx.x;   // big tiles first
    const int bh = blockIdx.y;
    const int b = bh >> 4, h = bh & 15;
    const float* qb = qkv + (size_t)b * S_ * QKVD + h * DH_;
    const float* kb = qb + D_;
    const float* vb = qb + 2 * D_;
    float* cb = ctx + (size_t)b * S_ * D_ + h * DH_;

    const int tid = threadIdx.x, lane = tid & 31, warp = tid >> 5;   // warp 0..3
    const int g = lane >> 2, t = lane & 3;
    const int rowBase = qt * 128;
    const int wrow = warp * 32;            // 32 q-rows per warp
    const int ktmax = 2 * qt + 2;

    // ---- Q prologue: each warp stages its own 32 rows
    #pragma unroll
    for (int u = 0; u < 16; u++) {
        int idx = u * 32 + lane;
        int r = idx >> 4, c4 = (idx & 15) * 4;
        cpasync16(&Ps[(wrow + r) * SK + c4],
                  &qb[(size_t)(rowBase + wrow + r) * QKVD + c4]);
    }
    asm volatile("cp.async.commit_group;");
    asm volatile("cp.async.wait_group 0;");
    __syncwarp();

    unsigned qa[2][8][4];
    #pragma unroll
    for (int mt = 0; mt < 2; mt++) {
        int wr = wrow + 16 * mt;
        #pragma unroll
        for (int ks = 0; ks < 8; ks++) {
            qa[mt][ks][0] = __float_as_uint(0.125f * Ps[(wr + g)     * SK + 8*ks + t]);
            qa[mt][ks][1] = __float_as_uint(0.125f * Ps[(wr + g + 8) * SK + 8*ks + t]);
            qa[mt][ks][2] = __float_as_uint(0.125f * Ps[(wr + g)     * SK + 8*ks + t + 4]);
            qa[mt][ks][3] = __float_as_uint(0.125f * Ps[(wr + g + 8) * SK + 8*ks + t + 4]);
        }
    }

    // ---- prefetch KV tile 0 into buffer 0
    {
        float* Ks = KV0;
        float* Vs = KV0 + 64 * SK;
        #pragma unroll
        for (int u = 0; u < 8; u++) {
            int idx = u * 128 + tid;
            int r = idx >> 4, c4 = (idx & 15) * 4;
            cpasync16(&Ks[r * SK + c4], &kb[(size_t)r * QKVD + c4]);
            cpasync16(&Vs[r * SV + c4], &vb[(size_t)r * QKVD + c4]);
        }
        asm volatile("cp.async.commit_group;");
    }

    float o[2][8][4];
    #pragma unroll
    for (int mt = 0; mt < 2; mt++)
        #pragma unroll
        for (int nt = 0; nt < 8; nt++)
            #pragma unroll
            for (int e = 0; e < 4; e++) o[mt][nt][e] = 0.f;
    float mrow[2][2] = { {-1e30f, -1e30f}, {-1e30f, -1e30f} };
    float lrow[2][2] = { {0.f, 0.f}, {0.f, 0.f} };
    int rown[2][2];
    #pragma unroll
    for (int mt = 0; mt < 2; mt++) {
        rown[mt][0] = rowBase + wrow + 16 * mt + g;
        rown[mt][1] = rown[mt][0] + 8;
    }

    for (int kt = 0; kt < ktmax; kt++) {
        __syncthreads();                       // prev compute done on buf^1
        if (kt + 1 < ktmax) {                  // prefetch next tile into buf^1
            float* Ks = KV0 + ((kt + 1) & 1) * KVBUF;
            float* Vs = Ks + 64 * SK;
            #pragma unroll
            for (int u = 0; u < 8; u++) {
                int idx = u * 128 + tid;
                int r = idx >> 4, c4 = (idx & 15) * 4;
                cpasync16(&Ks[r * SK + c4], &kb[(size_t)((kt + 1) * 64 + r) * QKVD + c4]);
                cpasync16(&Vs[r * SV + c4], &vb[(size_t)((kt + 1) * 64 + r) * QKVD + c4]);
            }
            asm volatile("cp.async.commit_group;");
            asm volatile("cp.async.wait_group 1;");
        } else {
            asm volatile("cp.async.wait_group 0;");
        }
        __syncthreads();                       // tile kt visible to all

        const float* Ks = KV0 + (kt & 1) * KVBUF;
        const float* Vs = Ks + 64 * SK;

        // ---- S = Q K^T: each K fragment reused across both m-tiles
        float sc[2][8][4];
        #pragma unroll
        for (int mt = 0; mt < 2; mt++)
            #pragma unroll
            for (int nt = 0; nt < 8; nt++)
                sc[mt][nt][0] = sc[mt][nt][1] = sc[mt][nt][2] = sc[mt][nt][3] = 0.f;
        #pragma unroll
        for (int nt = 0; nt < 8; nt++) {
            #pragma unroll
            for (int ks = 0; ks < 8; ks++) {
                unsigned bb[2];
                bb[0] = __float_as_uint(Ks[(8*nt + g) * SK + 8*ks + t]);
                bb[1] = __float_as_uint(Ks[(8*nt + g) * SK + 8*ks + t + 4]);
                mma_tf32(sc[0][nt], qa[0][ks], bb);
                mma_tf32(sc[1][nt], qa[1][ks], bb);
            }
        }

        // ---- mask + online softmax (per m-tile)
        const int colb = kt * 64 + 2 * t;
        #pragma unroll
        for (int mt = 0; mt < 2; mt++) {
            float mx0 = -1e30f, mx1 = -1e30f;
            #pragma unroll
            for (int nt = 0; nt < 8; nt++) {
                int c0 = colb + 8 * nt;
                float v0 = sc[mt][nt][0]; if (c0     > rown[mt][0]) v0 = -1e30f;
                float v1 = sc[mt][nt][1]; if (c0 + 1 > rown[mt][0]) v1 = -1e30f;
                float v2 = sc[mt][nt][2]; if (c0     > rown[mt][1]) v2 = -1e30f;
                float v3 = sc[mt][nt][3]; if (c0 + 1 > rown[mt][1]) v3 = -1e30f;
                sc[mt][nt][0] = v0; sc[mt][nt][1] = v1;
                sc[mt][nt][2] = v2; sc[mt][nt][3] = v3;
                mx0 = fmaxf(mx0, fmaxf(v0, v1));
                mx1 = fmaxf(mx1, fmaxf(v2, v3));
            }
            mx0 = fmaxf(mx0, __shfl_xor_sync(0xffffffffu, mx0, 1));
            mx0 = fmaxf(mx0, __shfl_xor_sync(0xffffffffu, mx0, 2));
            mx1 = fmaxf(mx1, __shfl_xor_sync(0xffffffffu, mx1, 1));
            mx1 = fmaxf(mx1, __shfl_xor_sync(0xffffffffu, mx1, 2));

            float mn0 = fmaxf(mrow[mt][0], mx0), mn1 = fmaxf(mrow[mt][1], mx1);
            float s0 = __expf(mrow[mt][0] - mn0), s1 = __expf(mrow[mt][1] - mn1);
            mrow[mt][0] = mn0; mrow[mt][1] = mn1;

            int wr = wrow + 16 * mt;
            float sum0 = 0.f, sum1 = 0.f;
            #pragma unroll
            for (int nt = 0; nt < 8; nt++) {
                float p0 = __expf(sc[mt][nt][0] - mn0);
                float p1 = __expf(sc[mt][nt][1] - mn0);
                float p2 = __expf(sc[mt][nt][2] - mn1);
                float p3 = __expf(sc[mt][nt][3] - mn1);
                sum0 += p0 + p1; sum1 += p2 + p3;
                *(float2*)&Ps[(wr + g)     * SK + 8*nt + 2*t] =
                    make_float2(rnd_tf32(p0), rnd_tf32(p1));
                *(float2*)&Ps[(wr + g + 8) * SK + 8*nt + 2*t] =
                    make_float2(rnd_tf32(p2), rnd_tf32(p3));
            }
            sum0 += __shfl_xor_sync(0xffffffffu, sum0, 1);
            sum0 += __shfl_xor_sync(0xffffffffu, sum0, 2);
            sum1 += __shfl_xor_sync(0xffffffffu, sum1, 1);
            sum1 += __shfl_xor_sync(0xffffffffu, sum1, 2);
            lrow[mt][0] = lrow[mt][0] * s0 + sum0;
            lrow[mt][1] = lrow[mt][1] * s1 + sum1;

            #pragma unroll
            for (int nt = 0; nt < 8; nt++) {
                o[mt][nt][0] *= s0; o[mt][nt][1] *= s0;
                o[mt][nt][2] *= s1; o[mt][nt][3] *= s1;
            }
        }
        __syncwarp();                          // P visible within warp

        // ---- O += P @ V: V fragments reused across both m-tiles
        #pragma unroll
        for (int ks = 0; ks < 8; ks++) {
            unsigned pa[2][4];
            #pragma unroll
            for (int mt = 0; mt < 2; mt++) {
                int wr = wrow + 16 * mt;
                pa[mt][0] = __float_as_uint(Ps[(wr + g)     * SK + 8*ks + t]);
                pa[mt][1] = __float_as_uint(Ps[(wr + g + 8) * SK + 8*ks + t]);
                pa[mt][2] = __float_as_uint(Ps[(wr + g)     * SK + 8*ks + t + 4]);
                pa[mt][3] = __float_as_uint(Ps[(wr + g + 8) * SK + 8*ks + t + 4]);
            }
            #pragma unroll
            for (int nt = 0; nt < 8; nt++) {
                unsigned bb[2];
                bb[0] = __float_as_uint(Vs[(8*ks + t)     * SV + 8*nt + g]);
                bb[1] = __float_as_uint(Vs[(8*ks + t + 4) * SV + 8*nt + g]);
                mma_tf32(o[0][nt], pa[0], bb);
                mma_tf32(o[1][nt], pa[1], bb);
            }
        }
    }

    // ---- epilogue: O / l, tf32-rounded (feeds O-proj GEMM)
    #pragma unroll
    for (int mt = 0; mt < 2; mt++) {
        float inv0 = __fdividef(1.f, lrow[mt][0]);
        float inv1 = __fdividef(1.f, lrow[mt][1]);
        #pragma unroll
        for (int nt = 0; nt < 8; nt++) {
            *(float2*)&cb[(size_t)rown[mt][0] * D_ + 8*nt + 2*t] =
                make_float2(rnd_tf32(o[mt][nt][0] * inv0), rnd_tf32(o[mt][nt][1] * inv0));
            *(float2*)&cb[(size_t)rown[mt][1] * D_ + 8*nt + 2*t] =
                make_float2(rnd_tf32(o[mt][nt][2] * inv1), rnd_tf32(o[mt][nt][3] * inv1));
        }
    }
}

// ---------------- launcher -------------------------------------------------------
extern "C" void kernel_launch(void* const* d_in, const int* in_sizes, int n_in,
                              void* d_out, int out_size)
{
    const float* x     = (const float*)d_in[0];
    const float* ln1_s = (const float*)d_in[1];
    const float* ln1_b = (const float*)d_in[2];
    const float* wq    = (const float*)d_in[3];
    const float* wk    = (const float*)d_in[4];
    const float* wv    = (const float*)d_in[5];
    const float* wo    = (const float*)d_in[6];
    const float* bo    = (const float*)d_in[7];
    const float* ln2_s = (const float*)d_in[8];
    const float* ln2_b = (const float*)d_in[9];
    const float* w1    = (const float*)d_in[10];
    const float* b1    = (const float*)d_in[11];
    const float* w2    = (const float*)d_in[12];
    const float* b2    = (const float*)d_in[13];
    float* out = (float*)d_out;

    float *ln, *qkv, *ctx, *h, *ffn, *pool;
    cudaGetSymbolAddress((void**)&ln,   g_ln);
    cudaGetSymbolAddress((void**)&qkv,  g_qkv);
    cudaGetSymbolAddress((void**)&ctx,  g_ctx);
    cudaGetSymbolAddress((void**)&h,    g_h);
    cudaGetSymbolAddress((void**)&ffn,  g_ffn);
    cudaGetSymbolAddress((void**)&pool, g_pool);

    float* wqkvP = pool;            // [1024, 3072]

    cudaFuncSetAttribute(flash_attn_kernel,
                         cudaFuncAttributeMaxDynamicSharedMemorySize, FLASH_SMEM);
    cudaFuncSetAttribute(sgemm_tf32_kernel,
                         cudaFuncAttributeMaxDynamicSharedMemorySize, GEMM_SMEM);

    // 0) weight prep: pack QKV (one launch). wo/w1/w2 used raw (HW trunc).
    pack_qkv_kernel<<<3072, 256>>>(wq, wk, wv, wqkvP);

    // 1) ln1(x)
    ln_kernel<<<M_, 256>>>(x, ln1_s, ln1_b, ln);

    // 2) fused QKV projection (one GEMM, N=3072), output tf32-rounded
    dim3 gqkv(QKVD / 128, M_ / 128);
    sgemm_tf32_kernel<<<gqkv, 128, GEMM_SMEM>>>(ln, wqkvP, nullptr, nullptr, qkv,
                                                M_, QKVD, D_, 0, 1);

    // 3) fused flash attention -> ctx (tf32-rounded)
    flash_attn_kernel<<<dim3(S_/128, B_*H_), 128, FLASH_SMEM>>>(qkv, ctx);

    // 4) output projection + bias + residual -> h (raw wo)
    dim3 gp(D_ / 128, M_ / 128);
    sgemm_tf32_kernel<<<gp, 128, GEMM_SMEM>>>(ctx, wo, bo, x, h, M_, D_, D_, 0, 0);

    // 5) ln2(h)
    ln_kernel<<<M_, 256>>>(h, ln2_s, ln2_b, ln);

    // 6) FFN (raw w1/w2)
    dim3 gf1(DFF_ / 128, M_ / 128);
    sgemm_tf32_kernel<<<gf1, 128, GEMM_SMEM>>>(ln, w1, b1, nullptr, ffn, M_, DFF_, D_, 1, 1);
    sgemm_tf32_kernel<<<gp, 128, GEMM_SMEM>>>(ffn, w2, b2, h, out, M_, D_, DFF_, 0, 0);
}

// round 15
// speedup vs baseline: 1.0804x; 1.0070x over previous
#include <cuda_runtime.h>
#include <math.h>
#include <stdint.h>

#define B_   2
#define S_   2048
#define D_   1024
#define H_   16
#define DH_  64
#define DFF_ 4096
#define M_   (B_*S_)    // 4096 tokens
#define QKVD 3072

// ---------------- scratch (static device allocations) ---------------------------
__device__ float g_ln [M_ * D_];
__device__ float g_qkv[(size_t)M_ * QKVD];              // 48 MB
__device__ float g_ctx[M_ * D_];
__device__ float g_h  [M_ * D_];
__device__ float g_ffn[(size_t)M_ * DFF_];              // 64 MB
__device__ float g_pool[4 * 1024 * 1024];               // packed QKV weights

// ---------------- helpers --------------------------------------------------------
__device__ __forceinline__ unsigned f2tf32(float x) {
    unsigned r;
    asm("cvt.rna.tf32.f32 %0, %1;" : "=r"(r) : "f"(x));
    return r;
}
__device__ __forceinline__ float rnd_tf32(float x) {
    return __uint_as_float(f2tf32(x));
}
__device__ __forceinline__ void mma_tf32(float* c, const unsigned* a, const unsigned* b) {
    asm volatile(
        "mma.sync.aligned.m16n8k8.row.col.f32.tf32.tf32.f32 "
        "{%0,%1,%2,%3}, {%4,%5,%6,%7}, {%8,%9}, {%0,%1,%2,%3};"
        : "+f"(c[0]), "+f"(c[1]), "+f"(c[2]), "+f"(c[3])
        : "r"(a[0]), "r"(a[1]), "r"(a[2]), "r"(a[3]), "r"(b[0]), "r"(b[1]));
}
__device__ __forceinline__ void cpasync16(float* smem, const float* gmem) {
    unsigned s = (unsigned)__cvta_generic_to_shared(smem);
    asm volatile("cp.async.cg.shared.global [%0], [%1], 16;" :: "r"(s), "l"(gmem));
}

// ---------------- weight prep: pack Q,K,V into [1024, 3072] in ONE launch --------
__global__ void pack_qkv_kernel(const float* __restrict__ wq,
                                const float* __restrict__ wk,
                                const float* __restrict__ wv,
                                float* __restrict__ out)
{
    int which = blockIdx.x >> 10;               // 0..2
    int blk   = blockIdx.x & 1023;
    const float* in = (which == 0) ? wq : (which == 1) ? wk : wv;
    int off4 = which * 256;

    int i = blk * 256 + threadIdx.x;            // over 1024*256 float4s
    int k = i >> 8, n4 = i & 255;
    float4 a = ((const float4*)in)[i];
    a.x = rnd_tf32(a.x); a.y = rnd_tf32(a.y);
    a.z = rnd_tf32(a.z); a.w = rnd_tf32(a.w);
    ((float4*)(out + (size_t)k * QKVD))[off4 + n4] = a;
}

// ---------------- LayerNorm: one-pass, float4-per-thread, shuffle reduce ---------
__global__ void ln_kernel(const float* __restrict__ x,
                          const float* __restrict__ sc,
                          const float* __restrict__ sh,
                          float* __restrict__ out)
{
    int row = blockIdx.x;
    const int tid = threadIdx.x;             // 256 threads, D = 1024 = 256*4
    float4 v = *(const float4*)(x + (size_t)row * D_ + tid * 4);

    float s  = v.x + v.y + v.z + v.w;
    float s2 = v.x*v.x + v.y*v.y + v.z*v.z + v.w*v.w;
    #pragma unroll
    for (int o = 16; o > 0; o >>= 1) {
        s  += __shfl_xor_sync(0xffffffffu, s,  o);
        s2 += __shfl_xor_sync(0xffffffffu, s2, o);
    }
    __shared__ float ws[8], ws2[8];
    int warp = tid >> 5, lane = tid & 31;
    if (lane == 0) { ws[warp] = s; ws2[warp] = s2; }
    __syncthreads();
    if (warp == 0) {
        float a  = (lane < 8) ? ws[lane]  : 0.f;
        float a2 = (lane < 8) ? ws2[lane] : 0.f;
        #pragma unroll
        for (int o = 4; o > 0; o >>= 1) {
            a  += __shfl_xor_sync(0xffffffffu, a,  o);
            a2 += __shfl_xor_sync(0xffffffffu, a2, o);
        }
        if (lane == 0) { ws[0] = a; ws2[0] = a2; }
    }
    __syncthreads();

    float mean = ws[0] * (1.0f / D_);
    float var  = ws2[0] * (1.0f / D_) - mean * mean;
    float inv  = rsqrtf(var + 1e-5f);

    float4 g = *(const float4*)(sc + tid * 4);
    float4 bsh = *(const float4*)(sh + tid * 4);
    float4 o4;
    o4.x = rnd_tf32((v.x - mean) * inv * g.x + bsh.x);
    o4.y = rnd_tf32((v.y - mean) * inv * g.y + bsh.y);
    o4.z = rnd_tf32((v.z - mean) * inv * g.z + bsh.z);
    o4.w = rnd_tf32((v.w - mean) * inv * g.w + bsh.w);
    *(float4*)(out + (size_t)row * D_ + tid * 4) = o4;
}

// ---------------- TF32 mma.sync GEMM: 4 warps @ 64x64, 5-stage ring --------------
#define AS_STRIDE 20
#define BS_STRIDE 136
#define AS_BUF (128 * AS_STRIDE)
#define BS_BUF (16 * BS_STRIDE)
#define STG_FLOATS (AS_BUF + BS_BUF)
#define GSTAGES 5
#define GEMM_SMEM (GSTAGES * STG_FLOATS * 4)   // 94720 B

__global__ __launch_bounds__(128, 2)
void sgemm_tf32_kernel(const float* __restrict__ A,
                       const float* __restrict__ Bm,
                       const float* __restrict__ bias,   // may be null
                       const float* __restrict__ res,    // may be null
                       float* __restrict__ C,
                       int M, int N, int K, int gelu, int roundOut)
{
    extern __shared__ float sm[];

    const int tid  = threadIdx.x;
    const int lane = tid & 31;
    const int warp = tid >> 5;       // 0..3
    const int g    = lane >> 2;
    const int t    = lane & 3;
    const int warpRow = warp >> 1;
    const int warpCol = warp & 1;

    const int rowBase = blockIdx.y * 128;
    const int colBase = blockIdx.x * 128;

    float acc[4][8][4];
    #pragma unroll
    for (int i = 0; i < 4; i++)
        #pragma unroll
        for (int j = 0; j < 8; j++)
            #pragma unroll
            for (int r = 0; r < 4; r++) acc[i][j][r] = 0.f;

    const int nIter = K / 16;

    // prologue: fill stages 0..3
    #pragma unroll
    for (int p = 0; p < GSTAGES - 1; p++) {
        float* As = sm + p * STG_FLOATS;
        float* Bs = As + AS_BUF;
        int k0 = p * 16;
        #pragma unroll
        for (int u = 0; u < 4; u++) {
            int idx = u * 128 + tid;
            int ar = idx >> 2, ac = (idx & 3) * 4;
            cpasync16(&As[ar * AS_STRIDE + ac], &A[(size_t)(rowBase + ar) * K + k0 + ac]);
            int br = idx >> 5, bc = (idx & 31) * 4;
            cpasync16(&Bs[br * BS_STRIDE + bc], &Bm[(size_t)(k0 + br) * N + colBase + bc]);
        }
        asm volatile("cp.async.commit_group;");
    }

    int sr = 0;                        // read stage
    int swr = GSTAGES - 1;             // write stage (for kt+4)
    for (int kt = 0; kt < nIter; ++kt) {
        if (kt + 4 <= nIter)      { asm volatile("cp.async.wait_group 3;"); }
        else if (kt + 3 == nIter) { asm volatile("cp.async.wait_group 2;"); }
        else if (kt + 2 == nIter) { asm volatile("cp.async.wait_group 1;"); }
        else                      { asm volatile("cp.async.wait_group 0;"); }
        __syncthreads();

        if (kt + 4 < nIter) {
            float* As = sm + swr * STG_FLOATS;
            float* Bs = As + AS_BUF;
            int k0 = (kt + 4) * 16;
            #pragma unroll
            for (int u = 0; u < 4; u++) {
                int idx = u * 128 + tid;
                int ar = idx >> 2, ac = (idx & 3) * 4;
                cpasync16(&As[ar * AS_STRIDE + ac], &A[(size_t)(rowBase + ar) * K + k0 + ac]);
                int br = idx >> 5, bc = (idx & 31) * 4;
                cpasync16(&Bs[br * BS_STRIDE + bc], &Bm[(size_t)(k0 + br) * N + colBase + bc]);
            }
            asm volatile("cp.async.commit_group;");
        }
        swr = (swr + 1 == GSTAGES) ? 0 : swr + 1;

        const float* As_ = sm + sr * STG_FLOATS;
        const float* Bs_ = As_ + AS_BUF;
        sr = (sr + 1 == GSTAGES) ? 0 : sr + 1;

        #pragma unroll
        for (int ks = 0; ks < 2; ks++) {
            const int k = ks * 8;
            unsigned afr[4][4], bfr[8][2];
            #pragma unroll
            for (int mt = 0; mt < 4; mt++) {
                int m = warpRow * 64 + mt * 16 + g;
                afr[mt][0] = __float_as_uint(As_[m * AS_STRIDE + k + t]);
                afr[mt][1] = __float_as_uint(As_[(m + 8) * AS_STRIDE + k + t]);
                afr[mt][2] = __float_as_uint(As_[m * AS_STRIDE + k + t + 4]);
                afr[mt][3] = __float_as_uint(As_[(m + 8) * AS_STRIDE + k + t + 4]);
            }
            #pragma unroll
            for (int nt = 0; nt < 8; nt++) {
                int n = warpCol * 64 + nt * 8 + g;
                bfr[nt][0] = __float_as_uint(Bs_[(k + t) * BS_STRIDE + n]);
                bfr[nt][1] = __float_as_uint(Bs_[(k + t + 4) * BS_STRIDE + n]);
            }
            #pragma unroll
            for (int mt = 0; mt < 4; mt++)
                #pragma unroll
                for (int nt = 0; nt < 8; nt++)
                    mma_tf32(acc[mt][nt], afr[mt], bfr[nt]);
        }
    }

    #pragma unroll
    for (int mt = 0; mt < 4; mt++) {
        #pragma unroll
        for (int nt = 0; nt < 8; nt++) {
            int r0 = rowBase + warpRow * 64 + mt * 16 + g;
            int c0 = colBase + warpCol * 64 + nt * 8 + 2 * t;
            #pragma unroll
            for (int half = 0; half < 2; half++) {
                int r = r0 + half * 8;
                float v0 = acc[mt][nt][2*half], v1 = acc[mt][nt][2*half+1];
                if (bias) { v0 += bias[c0]; v1 += bias[c0 + 1]; }
                if (gelu) {
                    float t0 = 1.5957691216057308f * v0 + 0.0713548162726009f * v0 * v0 * v0;
                    v0 = __fdividef(v0, 1.f + __expf(-t0));
                    float t1 = 1.5957691216057308f * v1 + 0.0713548162726009f * v1 * v1 * v1;
                    v1 = __fdividef(v1, 1.f + __expf(-t1));
                }
                if (res) {
                    float2 rr = *(const float2*)&res[(size_t)r * N + c0];
                    v0 += rr.x; v1 += rr.y;
                }
                if (roundOut) { v0 = rnd_tf32(v0); v1 = rnd_tf32(v1); }
                *(float2*)&C[(size_t)r * N + c0] = make_float2(v0, v1);
            }
        }
    }
}

// ---------------- fused flash attention: 4 warps, 32 q-rows/warp -----------------
// Exact-causal warp-tile skipping: warps whose 32 rows lie fully above the
// diagonal for a K/V tile skip S, softmax, and P·V for that tile.
#define SK 68
#define SV 72
#define KVBUF (64*SK + 64*SV)
#define FLASH_SMEM ((128*SK + 2*KVBUF) * 4)

__global__ __launch_bounds__(128)
void flash_attn_kernel(const float* __restrict__ qkv, float* __restrict__ ctx)
{
    extern __shared__ float sm[];
    float* Ps = sm;                       // 128 x SK (Q prologue, then P)
    float* KV0 = sm + 128 * SK;           // double-buffered K/V tiles

    const int qt = (int)(gridDim.x - 1) - (int)blockIdx.x;   // big tiles first
    const int bh = blockIdx.y;
    const int b = bh >> 4, h = bh & 15;
    const float* qb = qkv + (size_t)b * S_ * QKVD + h * DH_;
    const float* kb = qb + D_;
    const float* vb = qb + 2 * D_;
    float* cb = ctx + (size_t)b * S_ * D_ + h * DH_;

    const int tid = threadIdx.x, lane = tid & 31, warp = tid >> 5;   // warp 0..3
    const int g = lane >> 2, t = lane & 3;
    const int rowBase = qt * 128;
    const int wrow = warp * 32;            // 32 q-rows per warp
    const int ktmax = 2 * qt + 2;

    // ---- Q prologue: each warp stages its own 32 rows
    #pragma unroll
    for (int u = 0; u < 16; u++) {
        int idx = u * 32 + lane;
        int r = idx >> 4, c4 = (idx & 15) * 4;
        cpasync16(&Ps[(wrow + r) * SK + c4],
                  &qb[(size_t)(rowBase + wrow + r) * QKVD + c4]);
    }
    asm volatile("cp.async.commit_group;");
    asm volatile("cp.async.wait_group 0;");
    __syncwarp();

    unsigned qa[2][8][4];
    #pragma unroll
    for (int mt = 0; mt < 2; mt++) {
        int wr = wrow + 16 * mt;
        #pragma unroll
        for (int ks = 0; ks < 8; ks++) {
            qa[mt][ks][0] = __float_as_uint(0.125f * Ps[(wr + g)     * SK + 8*ks + t]);
            qa[mt][ks][1] = __float_as_uint(0.125f * Ps[(wr + g + 8) * SK + 8*ks + t]);
            qa[mt][ks][2] = __float_as_uint(0.125f * Ps[(wr + g)     * SK + 8*ks + t + 4]);
            qa[mt][ks][3] = __float_as_uint(0.125f * Ps[(wr + g + 8) * SK + 8*ks + t + 4]);
        }
    }

    // ---- prefetch KV tile 0 into buffer 0
    {
        float* Ks = KV0;
        float* Vs = KV0 + 64 * SK;
        #pragma unroll
        for (int u = 0; u < 8; u++) {
            int idx = u * 128 + tid;
            int r = idx >> 4, c4 = (idx & 15) * 4;
            cpasync16(&Ks[r * SK + c4], &kb[(size_t)r * QKVD + c4]);
            cpasync16(&Vs[r * SV + c4], &vb[(size_t)r * QKVD + c4]);
        }
        asm volatile("cp.async.commit_group;");
    }

    float o[2][8][4];
    #pragma unroll
    for (int mt = 0; mt < 2; mt++)
        #pragma unroll
        for (int nt = 0; nt < 8; nt++)
            #pragma unroll
            for (int e = 0; e < 4; e++) o[mt][nt][e] = 0.f;
    float mrow[2][2] = { {-1e30f, -1e30f}, {-1e30f, -1e30f} };
    float lrow[2][2] = { {0.f, 0.f}, {0.f, 0.f} };
    int rown[2][2];
    #pragma unroll
    for (int mt = 0; mt < 2; mt++) {
        rown[mt][0] = rowBase + wrow + 16 * mt + g;
        rown[mt][1] = rown[mt][0] + 8;
    }

    for (int kt = 0; kt < ktmax; kt++) {
        __syncthreads();                       // prev compute done on buf^1
        if (kt + 1 < ktmax) {                  // prefetch next tile into buf^1
            float* Ks = KV0 + ((kt + 1) & 1) * KVBUF;
            float* Vs = Ks + 64 * SK;
            #pragma unroll
            for (int u = 0; u < 8; u++) {
                int idx = u * 128 + tid;
                int r = idx >> 4, c4 = (idx & 15) * 4;
                cpasync16(&Ks[r * SK + c4], &kb[(size_t)((kt + 1) * 64 + r) * QKVD + c4]);
                cpasync16(&Vs[r * SV + c4], &vb[(size_t)((kt + 1) * 64 + r) * QKVD + c4]);
            }
            asm volatile("cp.async.commit_group;");
            asm volatile("cp.async.wait_group 1;");
        } else {
            asm volatile("cp.async.wait_group 0;");
        }
        __syncthreads();                       // tile kt visible to all

        // warp-uniform: does this warp have ANY unmasked element in tile kt?
        if (rowBase + wrow + 31 < kt * 64) continue;

        const float* Ks = KV0 + (kt & 1) * KVBUF;
        const float* Vs = Ks + 64 * SK;

        // ---- S = Q K^T: each K fragment reused across both m-tiles
        float sc[2][8][4];
        #pragma unroll
        for (int mt = 0; mt < 2; mt++)
            #pragma unroll
            for (int nt = 0; nt < 8; nt++)
                sc[mt][nt][0] = sc[mt][nt][1] = sc[mt][nt][2] = sc[mt][nt][3] = 0.f;
        #pragma unroll
        for (int nt = 0; nt < 8; nt++) {
            #pragma unroll
            for (int ks = 0; ks < 8; ks++) {
                unsigned bb[2];
                bb[0] = __float_as_uint(Ks[(8*nt + g) * SK + 8*ks + t]);
                bb[1] = __float_as_uint(Ks[(8*nt + g) * SK + 8*ks + t + 4]);
                mma_tf32(sc[0][nt], qa[0][ks], bb);
                mma_tf32(sc[1][nt], qa[1][ks], bb);
            }
        }

        // ---- mask + online softmax (per m-tile)
        const int colb = kt * 64 + 2 * t;
        #pragma unroll
        for (int mt = 0; mt < 2; mt++) {
            float mx0 = -1e30f, mx1 = -1e30f;
            #pragma unroll
            for (int nt = 0; nt < 8; nt++) {
                int c0 = colb + 8 * nt;
                float v0 = sc[mt][nt][0]; if (c0     > rown[mt][0]) v0 = -1e30f;
                float v1 = sc[mt][nt][1]; if (c0 + 1 > rown[mt][0]) v1 = -1e30f;
                float v2 = sc[mt][nt][2]; if (c0     > rown[mt][1]) v2 = -1e30f;
                float v3 = sc[mt][nt][3]; if (c0 + 1 > rown[mt][1]) v3 = -1e30f;
                sc[mt][nt][0] = v0; sc[mt][nt][1] = v1;
                sc[mt][nt][2] = v2; sc[mt][nt][3] = v3;
                mx0 = fmaxf(mx0, fmaxf(v0, v1));
                mx1 = fmaxf(mx1, fmaxf(v2, v3));
            }
            mx0 = fmaxf(mx0, __shfl_xor_sync(0xffffffffu, mx0, 1));
            mx0 = fmaxf(mx0, __shfl_xor_sync(0xffffffffu, mx0, 2));
            mx1 = fmaxf(mx1, __shfl_xor_sync(0xffffffffu, mx1, 1));
            mx1 = fmaxf(mx1, __shfl_xor_sync(0xffffffffu, mx1, 2));

            float mn0 = fmaxf(mrow[mt][0], mx0), mn1 = fmaxf(mrow[mt][1], mx1);
            float s0 = __expf(mrow[mt][0] - mn0), s1 = __expf(mrow[mt][1] - mn1);
            mrow[mt][0] = mn0; mrow[mt][1] = mn1;

            int wr = wrow + 16 * mt;
            float sum0 = 0.f, sum1 = 0.f;
            #pragma unroll
            for (int nt = 0; nt < 8; nt++) {
                float p0 = __expf(sc[mt][nt][0] - mn0);
                float p1 = __expf(sc[mt][nt][1] - mn0);
                float p2 = __expf(sc[mt][nt][2] - mn1);
                float p3 = __expf(sc[mt][nt][3] - mn1);
                sum0 += p0 + p1; sum1 += p2 + p3;
                *(float2*)&Ps[(wr + g)     * SK + 8*nt + 2*t] =
                    make_float2(rnd_tf32(p0), rnd_tf32(p1));
                *(float2*)&Ps[(wr + g + 8) * SK + 8*nt + 2*t] =
                    make_float2(rnd_tf32(p2), rnd_tf32(p3));
            }
            sum0 += __shfl_xor_sync(0xffffffffu, sum0, 1);
            sum0 += __shfl_xor_sync(0xffffffffu, sum0, 2);
            sum1 += __shfl_xor_sync(0xffffffffu, sum1, 1);
            sum1 += __shfl_xor_sync(0xffffffffu, sum1, 2);
            lrow[mt][0] = lrow[mt][0] * s0 + sum0;
            lrow[mt][1] = lrow[mt][1] * s1 + sum1;

            #pragma unroll
            for (int nt = 0; nt < 8; nt++) {
                o[mt][nt][0] *= s0; o[mt][nt][1] *= s0;
                o[mt][nt][2] *= s1; o[mt][nt][3] *= s1;
            }
        }
        __syncwarp();                          // P visible within warp

        // ---- O += P @ V: V fragments reused across both m-tiles
        #pragma unroll
        for (int ks = 0; ks < 8; ks++) {
            unsigned pa[2][4];
            #pragma unroll
            for (int mt = 0; mt < 2; mt++) {
                int wr = wrow + 16 * mt;
                pa[mt][0] = __float_as_uint(Ps[(wr + g)     * SK + 8*ks + t]);
                pa[mt][1] = __float_as_uint(Ps[(wr + g + 8) * SK + 8*ks + t]);
                pa[mt][2] = __float_as_uint(Ps[(wr + g)     * SK + 8*ks + t + 4]);
                pa[mt][3] = __float_as_uint(Ps[(wr + g + 8) * SK + 8*ks + t + 4]);
            }
            #pragma unroll
            for (int nt = 0; nt < 8; nt++) {
                unsigned bb[2];
                bb[0] = __float_as_uint(Vs[(8*ks + t)     * SV + 8*nt + g]);
                bb[1] = __float_as_uint(Vs[(8*ks + t + 4) * SV + 8*nt + g]);
                mma_tf32(o[0][nt], pa[0], bb);
                mma_tf32(o[1][nt], pa[1], bb);
            }
        }
    }

    // ---- epilogue: O / l, tf32-rounded (feeds O-proj GEMM)
    #pragma unroll
    for (int mt = 0; mt < 2; mt++) {
        float inv0 = __fdividef(1.f, lrow[mt][0]);
        float inv1 = __fdividef(1.f, lrow[mt][1]);
        #pragma unroll
        for (int nt = 0; nt < 8; nt++) {
            *(float2*)&cb[(size_t)rown[mt][0] * D_ + 8*nt + 2*t] =
                make_float2(rnd_tf32(o[mt][nt][0] * inv0), rnd_tf32(o[mt][nt][1] * inv0));
            *(float2*)&cb[(size_t)rown[mt][1] * D_ + 8*nt + 2*t] =
                make_float2(rnd_tf32(o[mt][nt][2] * inv1), rnd_tf32(o[mt][nt][3] * inv1));
        }
    }
}

// ---------------- launcher -------------------------------------------------------
extern "C" void kernel_launch(void* const* d_in, const int* in_sizes, int n_in,
                              void* d_out, int out_size)
{
    const float* x     = (const float*)d_in[0];
    const float* ln1_s = (const float*)d_in[1];
    const float* ln1_b = (const float*)d_in[2];
    const float* wq    = (const float*)d_in[3];
    const float* wk    = (const float*)d_in[4];
    const float* wv    = (const float*)d_in[5];
    const float* wo    = (const float*)d_in[6];
    const float* bo    = (const float*)d_in[7];
    const float* ln2_s = (const float*)d_in[8];
    const float* ln2_b = (const float*)d_in[9];
    const float* w1    = (const float*)d_in[10];
    const float* b1    = (const float*)d_in[11];
    const float* w2    = (const float*)d_in[12];
    const float* b2    = (const float*)d_in[13];
    float* out = (float*)d_out;

    float *ln, *qkv, *ctx, *h, *ffn, *pool;
    cudaGetSymbolAddress((void**)&ln,   g_ln);
    cudaGetSymbolAddress((void**)&qkv,  g_qkv);
    cudaGetSymbolAddress((void**)&ctx,  g_ctx);
    cudaGetSymbolAddress((void**)&h,    g_h);
    cudaGetSymbolAddress((void**)&ffn,  g_ffn);
    cudaGetSymbolAddress((void**)&pool, g_pool);

    float* wqkvP = pool;            // [1024, 3072]

    cudaFuncSetAttribute(flash_attn_kernel,
                         cudaFuncAttributeMaxDynamicSharedMemorySize, FLASH_SMEM);
    cudaFuncSetAttribute(sgemm_tf32_kernel,
                         cudaFuncAttributeMaxDynamicSharedMemorySize, GEMM_SMEM);

    // 0) weight prep: pack QKV (one launch). wo/w1/w2 used raw (HW trunc).
    pack_qkv_kernel<<<3072, 256>>>(wq, wk, wv, wqkvP);

    // 1) ln1(x)
    ln_kernel<<<M_, 256>>>(x, ln1_s, ln1_b, ln);

    // 2) fused QKV projection (one GEMM, N=3072), output tf32-rounded
    dim3 gqkv(QKVD / 128, M_ / 128);
    sgemm_tf32_kernel<<<gqkv, 128, GEMM_SMEM>>>(ln, wqkvP, nullptr, nullptr, qkv,
                                                M_, QKVD, D_, 0, 1);

    // 3) fused flash attention -> ctx (tf32-rounded)
    flash_attn_kernel<<<dim3(S_/128, B_*H_), 128, FLASH_SMEM>>>(qkv, ctx);

    // 4) output projection + bias + residual -> h (raw wo)
    dim3 gp(D_ / 128, M_ / 128);
    sgemm_tf32_kernel<<<gp, 128, GEMM_SMEM>>>(ctx, wo, bo, x, h, M_, D_, D_, 0, 0);

    // 5) ln2(h)
    ln_kernel<<<M_, 256>>>(h, ln2_s, ln2_b, ln);

    // 6) FFN (raw w1/w2)
    dim3 gf1(DFF_ / 128, M_ / 128);
    sgemm_tf32_kernel<<<gf1, 128, GEMM_SMEM>>>(ln, w1, b1, nullptr, ffn, M_, DFF_, D_, 1, 1);
    sgemm_tf32_kernel<<<gp, 128, GEMM_SMEM>>>(ffn, w2, b2, h, out, M_, D_, DFF_, 0, 0);
}